// round 1
// baseline (speedup 1.0000x reference)
#include <cuda_runtime.h>
#include <math.h>

#define CB   2
#define CS   4096
#define CHID 2048
#define CH   16
#define CKV  4
#define CD   128
#define CNB  64
#define NEGV -1000000000.0f
#define QK_SCALE 0.08838834764831845f   // 1/sqrt(128)

// -------- scratch (static device memory; allocation-free rule) --------
static __device__ float g_Q[(size_t)CB*CS*CH*CD];    // 64 MB  [B,S,H,D]
static __device__ float g_K[(size_t)CB*CS*CKV*CD];   // 16 MB  [B,S,KV,D]
static __device__ float g_V[(size_t)CB*CS*CKV*CD];   // 16 MB
static __device__ float g_A[(size_t)CB*CS*CH*CD];    // 64 MB  attention out

// ============================================================
// SGEMM: C[M,N] = A[M,K] @ B[K,N], all row-major, M%128==0,
// N%128==0, K%8==0. 128x128 block, 8x8 per thread, 256 threads.
// ============================================================
__global__ __launch_bounds__(256) void sgemm_kernel(
    const float* __restrict__ A, const float* __restrict__ B,
    float* __restrict__ C, int M, int N, int K)
{
    __shared__ float As[8][128];
    __shared__ float Bs[8][128];
    const int tid = threadIdx.x;
    const int bx = blockIdx.x * 128;
    const int by = blockIdx.y * 128;
    const int tx = (tid & 15) * 8;
    const int ty = (tid >> 4) * 8;
    const int arow = tid >> 1;
    const int acol = (tid & 1) * 4;
    const int brow = tid >> 5;
    const int bcol = (tid & 31) * 4;
    const float* Ap = A + (size_t)(by + arow) * K + acol;
    const float* Bp = B + (size_t)brow * N + bx + bcol;

    float acc[8][8];
#pragma unroll
    for (int m = 0; m < 8; m++)
#pragma unroll
        for (int n = 0; n < 8; n++) acc[m][n] = 0.f;

    for (int k0 = 0; k0 < K; k0 += 8) {
        float4 av = *(const float4*)(Ap + k0);
        As[acol + 0][arow] = av.x;
        As[acol + 1][arow] = av.y;
        As[acol + 2][arow] = av.z;
        As[acol + 3][arow] = av.w;
        *(float4*)&Bs[brow][bcol] = *(const float4*)(Bp + (size_t)k0 * N);
        __syncthreads();
#pragma unroll
        for (int k = 0; k < 8; k++) {
            float ar[8], br[8];
#pragma unroll
            for (int m = 0; m < 8; m++) ar[m] = As[k][ty + m];
#pragma unroll
            for (int n = 0; n < 8; n++) br[n] = Bs[k][tx + n];
#pragma unroll
            for (int m = 0; m < 8; m++)
#pragma unroll
                for (int n = 0; n < 8; n++)
                    acc[m][n] = fmaf(ar[m], br[n], acc[m][n]);
        }
        __syncthreads();
    }
#pragma unroll
    for (int m = 0; m < 8; m++) {
#pragma unroll
        for (int n = 0; n < 8; n += 4) {
            float4 v = make_float4(acc[m][n], acc[m][n+1], acc[m][n+2], acc[m][n+3]);
            *(float4*)(C + (size_t)(by + ty + m) * N + bx + tx + n) = v;
        }
    }
}

// ============================================================
// RoPE (in place): X is [B*S, nh, D]; cos/sin are [B*S, D].
// out[d]     = x[d]*cos[d]    - x[d+64]*sin[d]        (d < 64)
// out[d+64]  = x[d+64]*cos[d+64] + x[d]*sin[d+64]
// Folds `scale` (1/sqrt(D) for Q, 1.0 for K).
// ============================================================
__global__ void rope_kernel(float* __restrict__ X, const float* __restrict__ cs,
                            const float* __restrict__ sn, int nh, float scale)
{
    int idx = blockIdx.x * blockDim.x + threadIdx.x;
    int total = CB * CS * nh * (CD / 2);
    if (idx >= total) return;
    int d = idx & 63;
    int h = (idx >> 6) % nh;
    int t = idx / (64 * nh);          // b*S + s
    const float* c = cs + (size_t)t * CD;
    const float* s = sn + (size_t)t * CD;
    float* x = X + ((size_t)t * nh + h) * CD;
    float x1 = x[d], x2 = x[d + 64];
    x[d]      = (x1 * c[d]      - x2 * s[d])      * scale;
    x[d + 64] = (x2 * c[d + 64] + x1 * s[d + 64]) * scale;
}

// ============================================================
// Sparse attention. grid = (NB, H, B), 256 threads.
// One CTA handles a 64-query block against 8 key chunks:
//   chunks 0..3: local window blocks i-3..i (chunk 3 = intra/causal)
//   chunks 4..7: strided global blocks (reference _global_idx logic)
// Online softmax; O accumulator in registers (4 rows x 8 cols/thread).
// Q pre-scaled by 1/sqrt(D) in rope.
// ============================================================
#define LDK 129                         // K smem row stride (conflict pad)
#define ATTN_SMEM_FLOATS (64*128 + 64*LDK + 64*128 + 64*64 + 4*64)
#define ATTN_SMEM_BYTES  (ATTN_SMEM_FLOATS * 4)

__global__ __launch_bounds__(256) void attn_kernel(
    const float* __restrict__ Q, const float* __restrict__ K,
    const float* __restrict__ V, const float* __restrict__ am,
    float* __restrict__ Aout)
{
    extern __shared__ float smem[];
    float* Qs  = smem;                  // [64][128]
    float* Ks  = Qs  + 64 * 128;        // [64][LDK]
    float* Vs  = Ks  + 64 * LDK;        // [64][128]
    float* Ps  = Vs  + 64 * 128;        // [64][64]
    float* m_s = Ps  + 64 * 64;         // [64]
    float* l_s = m_s + 64;              // [64]
    float* a_s = l_s + 64;              // [64] alpha
    float* km_s= a_s + 64;              // [64]

    const int i = blockIdx.x, h = blockIdx.y, b = blockIdx.z;
    const int kvh = h >> 2;             // H/KV = 4
    const int tid = threadIdx.x;
    const int tr  = tid >> 4;           // 0..15 (row group of 4)
    const int tc  = tid & 15;           // 0..15
    const int row0 = tr * 4;

    // ---- load Q tile (scaled already) ----
    const float* qg = Q + (((size_t)b * CS + (size_t)i * 64) * CH + h) * CD;
    for (int e = tid; e < 64 * 32; e += 256) {
        int t = e >> 5, d4 = (e & 31) << 2;
        *(float4*)(Qs + t * 128 + d4) = *(const float4*)(qg + (size_t)t * CH * CD + d4);
    }
    if (tid < 64) { m_s[tid] = -3.0e38f; l_s[tid] = 0.f; }

    float O[4][8];
#pragma unroll
    for (int j = 0; j < 4; j++)
#pragma unroll
        for (int n = 0; n < 8; n++) O[j][n] = 0.f;

    __syncthreads();

    for (int c = 0; c < 8; c++) {
        int kb; bool intra = false; bool valid;
        if (c < 4) {
            kb = i - 3 + c;
            valid = (kb >= 0);
            intra = (c == 3);
        } else {
            int lo = (i > 32) ? (i - 32) : 0;
            int cnt = (i - lo + 3) >> 2;            // #candidates (stride 4)
            int j = cnt - 8 + c;                    // cnt - 4 + (c-4)
            valid = (i >= 1) && (j >= 0);
            kb = lo + 4 * j;
        }
        if (!valid) continue;

        // ---- load K (padded stride), V, key mask ----
        const float* kg = K + (((size_t)b * CS + (size_t)kb * 64) * CKV + kvh) * CD;
        const float* vg = V + (((size_t)b * CS + (size_t)kb * 64) * CKV + kvh) * CD;
        for (int e = tid; e < 64 * 32; e += 256) {
            int t = e >> 5, d4 = (e & 31) << 2;
            float4 kv = *(const float4*)(kg + (size_t)t * CKV * CD + d4);
            float* kd = Ks + t * LDK + d4;
            kd[0] = kv.x; kd[1] = kv.y; kd[2] = kv.z; kd[3] = kv.w;
            *(float4*)(Vs + t * 128 + d4) = *(const float4*)(vg + (size_t)t * CKV * CD + d4);
        }
        if (tid < 64) km_s[tid] = am[(size_t)b * CS + (size_t)kb * 64 + tid];
        __syncthreads();

        // ---- scores: 4x4 micro-tile per thread ----
        float acc[4][4];
#pragma unroll
        for (int j = 0; j < 4; j++)
#pragma unroll
            for (int n = 0; n < 4; n++) acc[j][n] = 0.f;
        const float* qp = Qs + row0 * 128;
        const float* kp = Ks + (tc * 4) * LDK;
#pragma unroll 4
        for (int d = 0; d < 128; d++) {
            float qv[4], kv[4];
#pragma unroll
            for (int j = 0; j < 4; j++) qv[j] = qp[j * 128 + d];
#pragma unroll
            for (int n = 0; n < 4; n++) kv[n] = kp[n * LDK + d];
#pragma unroll
            for (int j = 0; j < 4; j++)
#pragma unroll
                for (int n = 0; n < 4; n++)
                    acc[j][n] = fmaf(qv[j], kv[n], acc[j][n]);
        }

        // ---- mask + online softmax (row groups of 16 lanes) ----
#pragma unroll
        for (int j = 0; j < 4; j++) {
            int t = row0 + j;
#pragma unroll
            for (int n = 0; n < 4; n++) {
                int s = tc * 4 + n;
                float km = km_s[s];
                acc[j][n] += (1.0f - km) * NEGV;
                if (intra && s > t) acc[j][n] += NEGV;
            }
            float mx = fmaxf(fmaxf(acc[j][0], acc[j][1]), fmaxf(acc[j][2], acc[j][3]));
#pragma unroll
            for (int o = 1; o < 16; o <<= 1)
                mx = fmaxf(mx, __shfl_xor_sync(0xffffffffu, mx, o));
            float mo = m_s[t];
            float mn = fmaxf(mo, mx);
            float p[4], ps = 0.f;
#pragma unroll
            for (int n = 0; n < 4; n++) { p[n] = __expf(acc[j][n] - mn); ps += p[n]; }
#pragma unroll
            for (int o = 1; o < 16; o <<= 1)
                ps += __shfl_xor_sync(0xffffffffu, ps, o);
            if (tc == 0) {
                float al = __expf(mo - mn);
                a_s[t] = al;
                l_s[t] = l_s[t] * al + ps;
                m_s[t] = mn;
            }
            *(float4*)(Ps + t * 64 + tc * 4) = make_float4(p[0], p[1], p[2], p[3]);
        }
        __syncwarp();

        // ---- O = O*alpha + P @ V  (rows row0..row0+3, cols tc*8..tc*8+7) ----
        float alpha[4];
#pragma unroll
        for (int j = 0; j < 4; j++) alpha[j] = a_s[row0 + j];
#pragma unroll
        for (int j = 0; j < 4; j++)
#pragma unroll
            for (int n = 0; n < 8; n++) O[j][n] *= alpha[j];

        const float* pp = Ps + row0 * 64;
        const float* vp = Vs + tc * 8;
#pragma unroll 2
        for (int s = 0; s < 64; s++) {
            float pr[4];
#pragma unroll
            for (int j = 0; j < 4; j++) pr[j] = pp[j * 64 + s];
            float4 va = *(const float4*)(vp + s * 128);
            float4 vb = *(const float4*)(vp + s * 128 + 4);
            float vv[8] = {va.x, va.y, va.z, va.w, vb.x, vb.y, vb.z, vb.w};
#pragma unroll
            for (int j = 0; j < 4; j++)
#pragma unroll
                for (int n = 0; n < 8; n++)
                    O[j][n] = fmaf(pr[j], vv[n], O[j][n]);
        }
        __syncthreads();
    }

    // ---- normalize + write [B,S,H,D] ----
    float* og = Aout + (((size_t)b * CS + (size_t)i * 64) * CH + h) * CD;
#pragma unroll
    for (int j = 0; j < 4; j++) {
        float linv = 1.0f / l_s[row0 + j];
        float* orow = og + (size_t)(row0 + j) * CH * CD + tc * 8;
        float4 va = make_float4(O[j][0]*linv, O[j][1]*linv, O[j][2]*linv, O[j][3]*linv);
        float4 vb = make_float4(O[j][4]*linv, O[j][5]*linv, O[j][6]*linv, O[j][7]*linv);
        *(float4*)(orow) = va;
        *(float4*)(orow + 4) = vb;
    }
}

// ============================================================
// launcher
// ============================================================
extern "C" void kernel_launch(void* const* d_in, const int* in_sizes, int n_in,
                              void* d_out, int out_size)
{
    (void)in_sizes; (void)n_in; (void)out_size;
    const float* hidden = (const float*)d_in[0];
    const float* cosb   = (const float*)d_in[1];
    const float* sinb   = (const float*)d_in[2];
    const float* amask  = (const float*)d_in[3];
    const float* Wq     = (const float*)d_in[4];
    const float* Wk     = (const float*)d_in[5];
    const float* Wv     = (const float*)d_in[6];
    const float* Wo     = (const float*)d_in[7];
    float* out = (float*)d_out;

    float *Qp, *Kp, *Vp, *Ap;
    cudaGetSymbolAddress((void**)&Qp, g_Q);
    cudaGetSymbolAddress((void**)&Kp, g_K);
    cudaGetSymbolAddress((void**)&Vp, g_V);
    cudaGetSymbolAddress((void**)&Ap, g_A);

    const int M = CB * CS;              // 8192

    // QKV projections
    sgemm_kernel<<<dim3(CHID / 128, M / 128), 256>>>(hidden, Wq, Qp, M, CH * CD, CHID);
    sgemm_kernel<<<dim3((CKV * CD) / 128, M / 128), 256>>>(hidden, Wk, Kp, M, CKV * CD, CHID);
    sgemm_kernel<<<dim3((CKV * CD) / 128, M / 128), 256>>>(hidden, Wv, Vp, M, CKV * CD, CHID);

    // RoPE (scale folded into Q)
    rope_kernel<<<(CB * CS * CH * 64) / 256, 256>>>(Qp, cosb, sinb, CH, QK_SCALE);
    rope_kernel<<<(CB * CS * CKV * 64) / 256, 256>>>(Kp, cosb, sinb, CKV, 1.0f);

    // Attention
    cudaFuncSetAttribute(attn_kernel, cudaFuncAttributeMaxDynamicSharedMemorySize,
                         ATTN_SMEM_BYTES);
    attn_kernel<<<dim3(CNB, CH, CB), 256, ATTN_SMEM_BYTES>>>(Qp, Kp, Vp, amask, Ap);

    // Output projection
    sgemm_kernel<<<dim3(CHID / 128, M / 128), 256>>>(Ap, Wo, out, M, CHID, CHID);
}

// round 6
// speedup vs baseline: 1.3820x; 1.3820x over previous
#include <cuda_runtime.h>
#include <cuda_bf16.h>
#include <math.h>
#include <stdint.h>

#define CB   2
#define CS   4096
#define CHID 2048
#define CH   16
#define CKV  4
#define CD   128
#define CNB  64
#define NEGV -1000000000.0f
#define QK_SCALE 0.08838834764831845f   // 1/sqrt(128)

#define KK   2048
#define KK2  4096

// -------- scratch (static device memory; allocation-free rule) --------
static __device__ float g_Q[(size_t)CB*CS*CH*CD];          // [B,S,H,D] fp32
static __device__ float g_K[(size_t)CB*CS*CKV*CD];
static __device__ float g_V[(size_t)CB*CS*CKV*CD];
static __device__ float g_A[(size_t)CB*CS*CH*CD];          // attention out fp32
static __device__ __nv_bfloat16 g_hid2[(size_t)CB*CS*KK2]; // hidden hi|lo  [8192,4096]
static __device__ __nv_bfloat16 g_att2[(size_t)CB*CS*KK2]; // attn   hi|lo  [8192,4096]
static __device__ __nv_bfloat16 g_Wq2[(size_t)CHID*KK2];   // [N=2048, 2K]
static __device__ __nv_bfloat16 g_Wk2[(size_t)CKV*CD*KK2]; // [N=512,  2K]
static __device__ __nv_bfloat16 g_Wv2[(size_t)CKV*CD*KK2];
static __device__ __nv_bfloat16 g_Wo2[(size_t)CHID*KK2];

// ============================================================
// portable (non-'a') async-copy / ldmatrix / mma helpers
// ============================================================
__device__ __forceinline__ uint32_t smem_u32(const void* p) {
    uint32_t a;
    asm("{ .reg .u64 t; cvta.to.shared.u64 t, %1; cvt.u32.u64 %0, t; }"
        : "=r"(a) : "l"(p));
    return a;
}
__device__ __forceinline__ void cp16(uint32_t dst, const void* src) {
    asm volatile("cp.async.cg.shared.global [%0], [%1], 16;"
                 :: "r"(dst), "l"(src) : "memory");
}
__device__ __forceinline__ void cp_commit() {
    asm volatile("cp.async.commit_group;" ::: "memory");
}
template<int N_> __device__ __forceinline__ void cp_wait() {
    asm volatile("cp.async.wait_group %0;" :: "n"(N_) : "memory");
}
#define LDSM4(r, addr) \
    asm volatile("ldmatrix.sync.aligned.m8n8.x4.shared.b16 {%0,%1,%2,%3}, [%4];" \
        : "=r"((r)[0]), "=r"((r)[1]), "=r"((r)[2]), "=r"((r)[3]) : "r"(addr))
#define MMA16816(d, a, b0, b1) \
    asm volatile("mma.sync.aligned.m16n8k16.row.col.f32.bf16.bf16.f32 " \
        "{%0,%1,%2,%3}, {%4,%5,%6,%7}, {%8,%9}, {%0,%1,%2,%3};" \
        : "+f"((d)[0]), "+f"((d)[1]), "+f"((d)[2]), "+f"((d)[3]) \
        : "r"((a)[0]), "r"((a)[1]), "r"((a)[2]), "r"((a)[3]), "r"(b0), "r"(b1))

// ============================================================
// Split-bf16 mma.sync GEMM:
//   C[M,N] = Ah@Bh^T + Al@Bh^T + Ah@Bl^T   (fp32 accum in regs)
// A' [M,2K] bf16 row-major (hi|lo), B' [N,2K] bf16 row-major.
// CTA tile 128x128, BK=64, 3-stage cp.async pipeline.
// 8 warps (2x4): warp tile 64(M) x 32(N), m16n8k16.
// ============================================================
#define GSTG    3
#define GSTRIDE 32768                       // bytes per stage (A 16K + B 16K)
#define GEMM_SMEM_BYTES (GSTG * GSTRIDE + 1024)
#define NCHUNK  96                          // 3 passes x 32 chunks of K=64

__global__ __launch_bounds__(256) void mma_gemm(
    const __nv_bfloat16* __restrict__ Ab,
    const __nv_bfloat16* __restrict__ Bb,
    float* __restrict__ C, int M, int N)
{
    extern __shared__ char dsm_raw[];
    char* dsm = (char*)(((uintptr_t)dsm_raw + 1023) & ~(uintptr_t)1023);
    const uint32_t sb = smem_u32(dsm);

    const int tid  = threadIdx.x;
    const int lane = tid & 31;
    const int w    = tid >> 5;
    const int bx = blockIdx.x * 128;        // N offset
    const int by = blockIdx.y * 128;        // M offset
    const int wm = (w >> 2) * 64;           // warp M offset in tile
    const int wn = (w & 3) * 32;            // warp N offset in tile

    // ---- load-thread mapping: 8 chunks of 16B per thread (4 A + 4 B) ----
    // id = tid + i*256 : row = id/8 (0..127), ch = id%8 (16B column chunk)
    // ---- ldmatrix address precompute ----
    // A frags: per m-tile mt: rows wm+mt*16+(lane&15), col-byte 16*(lane>>4)
    uint32_t aAddr[4];
#pragma unroll
    for (int mt = 0; mt < 4; ++mt) {
        int r = wm + mt * 16 + (lane & 15);
        aAddr[mt] = sb + (uint32_t)r * 128;
    }
    const uint32_t aSw  = (uint32_t)(((wm + (lane & 15)) & 7) << 4);
    const uint32_t aCb0 = (uint32_t)((lane >> 4) * 16);
    // B frags: x4 covers 16 n-rows: n = wn + (lane&7) + ((lane>>4)<<3) (+16 per ld)
    uint32_t bAddr[2];
    {
        int n = wn + (lane & 7) + ((lane >> 4) << 3);
        bAddr[0] = sb + 16384 + (uint32_t)n * 128;
        bAddr[1] = bAddr[0] + 16 * 128;
    }
    const uint32_t bSw  = (uint32_t)((((lane & 7) + ((lane >> 4) << 3)) & 7) << 4);
    const uint32_t bCb0 = (uint32_t)(((lane >> 3) & 1) * 16);

    float acc[4][4][4];
#pragma unroll
    for (int mt = 0; mt < 4; ++mt)
#pragma unroll
        for (int nt = 0; nt < 4; ++nt)
#pragma unroll
            for (int e = 0; e < 4; ++e) acc[mt][nt][e] = 0.f;

    // ---- chunk loader ----
    auto load_chunk = [&](int c, int stage) {
        const int pass = c >> 5;
        const int k0   = (c & 31) * 64;
        const int aoff = (pass == 1) ? KK : 0;
        const int boff = (pass == 2) ? KK : 0;
        const uint32_t sBase = sb + (uint32_t)stage * GSTRIDE;
#pragma unroll
        for (int i = 0; i < 4; ++i) {
            const int id  = tid + i * 256;
            const int row = id >> 3;
            const int ch  = id & 7;
            const uint32_t soff = (uint32_t)row * 128
                                + (uint32_t)((ch * 16) ^ ((row & 7) << 4));
            cp16(sBase + soff,
                 Ab + (size_t)(by + row) * KK2 + aoff + k0 + ch * 8);
            cp16(sBase + 16384 + soff,
                 Bb + (size_t)(bx + row) * KK2 + boff + k0 + ch * 8);
        }
    };

    load_chunk(0, 0); cp_commit();
    load_chunk(1, 1); cp_commit();

    for (int c = 0; c < NCHUNK; ++c) {
        cp_wait<1>();
        __syncthreads();
        if (c + 2 < NCHUNK) load_chunk(c + 2, (c + 2) % GSTG);
        cp_commit();

        const uint32_t st = (uint32_t)(c % GSTG) * GSTRIDE;
#pragma unroll
        for (int j = 0; j < 4; ++j) {
            const uint32_t akb = ((uint32_t)(j * 32) + aCb0) ^ aSw;
            const uint32_t bkb = ((uint32_t)(j * 32) + bCb0) ^ bSw;
            uint32_t afr[4][4], bfr[2][4];
#pragma unroll
            for (int mt = 0; mt < 4; ++mt)
                LDSM4(afr[mt], aAddr[mt] + st + akb);
#pragma unroll
            for (int ld = 0; ld < 2; ++ld)
                LDSM4(bfr[ld], bAddr[ld] + st + bkb);
#pragma unroll
            for (int mt = 0; mt < 4; ++mt) {
#pragma unroll
                for (int nt = 0; nt < 4; ++nt) {
                    const uint32_t* bf = bfr[nt >> 1];
                    const int p = (nt & 1) * 2;
                    MMA16816(acc[mt][nt], afr[mt], bf[p], bf[p + 1]);
                }
            }
        }
        __syncthreads();
    }

    // ---- epilogue: fp32 regs -> C ----
    const int crow = lane >> 2;
    const int ccol = (lane & 3) * 2;
#pragma unroll
    for (int mt = 0; mt < 4; ++mt) {
#pragma unroll
        for (int nt = 0; nt < 4; ++nt) {
            float* cp = C + (size_t)(by + wm + mt * 16 + crow) * N
                          + bx + wn + nt * 8 + ccol;
            *(float2*)cp = make_float2(acc[mt][nt][0], acc[mt][nt][1]);
            *(float2*)(cp + (size_t)8 * N) = make_float2(acc[mt][nt][2], acc[mt][nt][3]);
        }
    }
}

// ============================================================
// fp32 [R,K] -> bf16 hi|lo [R,2K]
// ============================================================
__global__ void cvt_hilo_rows(const float* __restrict__ X,
                              __nv_bfloat16* __restrict__ Y, int total)
{
    int idx = blockIdx.x * blockDim.x + threadIdx.x;
    if (idx >= total) return;
    int r = idx >> 11;
    int k = idx & 2047;
    float x = X[idx];
    __nv_bfloat16 h = __float2bfloat16(x);
    float lo = x - __bfloat162float(h);
    Y[(size_t)r * KK2 + k] = h;
    Y[(size_t)r * KK2 + KK + k] = __float2bfloat16(lo);
}

// ============================================================
// W fp32 [K,N] -> Y bf16 [N,2K] (transpose + hi/lo split)
// ============================================================
__global__ void cvt_hilo_T(const float* __restrict__ W,
                           __nv_bfloat16* __restrict__ Y, int N)
{
    __shared__ float t[32][33];
    const int k0 = blockIdx.y * 32, n0 = blockIdx.x * 32;
    const int tx = threadIdx.x, ty = threadIdx.y;   // 32 x 8
#pragma unroll
    for (int j = 0; j < 32; j += 8)
        t[ty + j][tx] = W[(size_t)(k0 + ty + j) * N + n0 + tx];
    __syncthreads();
#pragma unroll
    for (int j = 0; j < 32; j += 8) {
        float x = t[tx][ty + j];
        __nv_bfloat16 h = __float2bfloat16(x);
        float lo = x - __bfloat162float(h);
        size_t row = (size_t)(n0 + ty + j) * KK2;
        Y[row + k0 + tx] = h;
        Y[row + KK + k0 + tx] = __float2bfloat16(lo);
    }
}

// ============================================================
// RoPE (in place): X is [B*S, nh, D]; cos/sin are [B*S, D].
// ============================================================
__global__ void rope_kernel(float* __restrict__ X, const float* __restrict__ cs,
                            const float* __restrict__ sn, int nh, float scale)
{
    int idx = blockIdx.x * blockDim.x + threadIdx.x;
    int total = CB * CS * nh * (CD / 2);
    if (idx >= total) return;
    int d = idx & 63;
    int h = (idx >> 6) % nh;
    int t = idx / (64 * nh);
    const float* c = cs + (size_t)t * CD;
    const float* s = sn + (size_t)t * CD;
    float* x = X + ((size_t)t * nh + h) * CD;
    float x1 = x[d], x2 = x[d + 64];
    x[d]      = (x1 * c[d]      - x2 * s[d])      * scale;
    x[d + 64] = (x2 * c[d + 64] + x1 * s[d + 64]) * scale;
}

// ============================================================
// Sparse attention (unchanged from passing R1 kernel)
// ============================================================
#define LDK 129
#define ATTN_SMEM_FLOATS (64*128 + 64*LDK + 64*128 + 64*64 + 4*64)
#define ATTN_SMEM_BYTES  (ATTN_SMEM_FLOATS * 4)

__global__ __launch_bounds__(256) void attn_kernel(
    const float* __restrict__ Q, const float* __restrict__ K,
    const float* __restrict__ V, const float* __restrict__ am,
    float* __restrict__ Aout)
{
    extern __shared__ float smem[];
    float* Qs  = smem;
    float* Ks  = Qs  + 64 * 128;
    float* Vs  = Ks  + 64 * LDK;
    float* Ps  = Vs  + 64 * 128;
    float* m_s = Ps  + 64 * 64;
    float* l_s = m_s + 64;
    float* a_s = l_s + 64;
    float* km_s= a_s + 64;

    const int i = blockIdx.x, h = blockIdx.y, b = blockIdx.z;
    const int kvh = h >> 2;
    const int tid = threadIdx.x;
    const int tr  = tid >> 4;
    const int tc  = tid & 15;
    const int row0 = tr * 4;

    const float* qg = Q + (((size_t)b * CS + (size_t)i * 64) * CH + h) * CD;
    for (int e = tid; e < 64 * 32; e += 256) {
        int t = e >> 5, d4 = (e & 31) << 2;
        *(float4*)(Qs + t * 128 + d4) = *(const float4*)(qg + (size_t)t * CH * CD + d4);
    }
    if (tid < 64) { m_s[tid] = -3.0e38f; l_s[tid] = 0.f; }

    float O[4][8];
#pragma unroll
    for (int j = 0; j < 4; j++)
#pragma unroll
        for (int n = 0; n < 8; n++) O[j][n] = 0.f;

    __syncthreads();

    for (int c = 0; c < 8; c++) {
        int kb; bool intra = false; bool valid;
        if (c < 4) {
            kb = i - 3 + c;
            valid = (kb >= 0);
            intra = (c == 3);
        } else {
            int lo = (i > 32) ? (i - 32) : 0;
            int cnt = (i - lo + 3) >> 2;
            int j = cnt - 8 + c;
            valid = (i >= 1) && (j >= 0);
            kb = lo + 4 * j;
        }
        if (!valid) continue;

        const float* kg = K + (((size_t)b * CS + (size_t)kb * 64) * CKV + kvh) * CD;
        const float* vg = V + (((size_t)b * CS + (size_t)kb * 64) * CKV + kvh) * CD;
        for (int e = tid; e < 64 * 32; e += 256) {
            int t = e >> 5, d4 = (e & 31) << 2;
            float4 kv = *(const float4*)(kg + (size_t)t * CKV * CD + d4);
            float* kd = Ks + t * LDK + d4;
            kd[0] = kv.x; kd[1] = kv.y; kd[2] = kv.z; kd[3] = kv.w;
            *(float4*)(Vs + t * 128 + d4) = *(const float4*)(vg + (size_t)t * CKV * CD + d4);
        }
        if (tid < 64) km_s[tid] = am[(size_t)b * CS + (size_t)kb * 64 + tid];
        __syncthreads();

        float acc[4][4];
#pragma unroll
        for (int j = 0; j < 4; j++)
#pragma unroll
            for (int n = 0; n < 4; n++) acc[j][n] = 0.f;
        const float* qp = Qs + row0 * 128;
        const float* kp = Ks + (tc * 4) * LDK;
#pragma unroll 4
        for (int d = 0; d < 128; d++) {
            float qv[4], kv[4];
#pragma unroll
            for (int j = 0; j < 4; j++) qv[j] = qp[j * 128 + d];
#pragma unroll
            for (int n = 0; n < 4; n++) kv[n] = kp[n * LDK + d];
#pragma unroll
            for (int j = 0; j < 4; j++)
#pragma unroll
                for (int n = 0; n < 4; n++)
                    acc[j][n] = fmaf(qv[j], kv[n], acc[j][n]);
        }

#pragma unroll
        for (int j = 0; j < 4; j++) {
            int t = row0 + j;
#pragma unroll
            for (int n = 0; n < 4; n++) {
                int s = tc * 4 + n;
                float km = km_s[s];
                acc[j][n] += (1.0f - km) * NEGV;
                if (intra && s > t) acc[j][n] += NEGV;
            }
            float mx = fmaxf(fmaxf(acc[j][0], acc[j][1]), fmaxf(acc[j][2], acc[j][3]));
#pragma unroll
            for (int o = 1; o < 16; o <<= 1)
                mx = fmaxf(mx, __shfl_xor_sync(0xffffffffu, mx, o));
            float mo = m_s[t];
            float mn = fmaxf(mo, mx);
            float p[4], ps = 0.f;
#pragma unroll
            for (int n = 0; n < 4; n++) { p[n] = __expf(acc[j][n] - mn); ps += p[n]; }
#pragma unroll
            for (int o = 1; o < 16; o <<= 1)
                ps += __shfl_xor_sync(0xffffffffu, ps, o);
            if (tc == 0) {
                float al = __expf(mo - mn);
                a_s[t] = al;
                l_s[t] = l_s[t] * al + ps;
                m_s[t] = mn;
            }
            *(float4*)(Ps + t * 64 + tc * 4) = make_float4(p[0], p[1], p[2], p[3]);
        }
        __syncwarp();

        float alpha[4];
#pragma unroll
        for (int j = 0; j < 4; j++) alpha[j] = a_s[row0 + j];
#pragma unroll
        for (int j = 0; j < 4; j++)
#pragma unroll
            for (int n = 0; n < 8; n++) O[j][n] *= alpha[j];

        const float* pp = Ps + row0 * 64;
        const float* vp = Vs + tc * 8;
#pragma unroll 2
        for (int s = 0; s < 64; s++) {
            float pr[4];
#pragma unroll
            for (int j = 0; j < 4; j++) pr[j] = pp[j * 64 + s];
            float4 va = *(const float4*)(vp + s * 128);
            float4 vb = *(const float4*)(vp + s * 128 + 4);
            float vv[8] = {va.x, va.y, va.z, va.w, vb.x, vb.y, vb.z, vb.w};
#pragma unroll
            for (int j = 0; j < 4; j++)
#pragma unroll
                for (int n = 0; n < 8; n++)
                    O[j][n] = fmaf(pr[j], vv[n], O[j][n]);
        }
        __syncthreads();
    }

    float* og = Aout + (((size_t)b * CS + (size_t)i * 64) * CH + h) * CD;
#pragma unroll
    for (int j = 0; j < 4; j++) {
        float linv = 1.0f / l_s[row0 + j];
        float* orow = og + (size_t)(row0 + j) * CH * CD + tc * 8;
        float4 va = make_float4(O[j][0]*linv, O[j][1]*linv, O[j][2]*linv, O[j][3]*linv);
        float4 vb = make_float4(O[j][4]*linv, O[j][5]*linv, O[j][6]*linv, O[j][7]*linv);
        *(float4*)(orow) = va;
        *(float4*)(orow + 4) = vb;
    }
}

// ============================================================
// launcher
// ============================================================
extern "C" void kernel_launch(void* const* d_in, const int* in_sizes, int n_in,
                              void* d_out, int out_size)
{
    (void)in_sizes; (void)n_in; (void)out_size;
    const float* hidden = (const float*)d_in[0];
    const float* cosb   = (const float*)d_in[1];
    const float* sinb   = (const float*)d_in[2];
    const float* amask  = (const float*)d_in[3];
    const float* Wq     = (const float*)d_in[4];
    const float* Wk     = (const float*)d_in[5];
    const float* Wv     = (const float*)d_in[6];
    const float* Wo     = (const float*)d_in[7];
    float* out = (float*)d_out;

    float *Qp, *Kp, *Vp, *Ap;
    __nv_bfloat16 *hid2, *att2, *wq2, *wk2, *wv2, *wo2;
    cudaGetSymbolAddress((void**)&Qp, g_Q);
    cudaGetSymbolAddress((void**)&Kp, g_K);
    cudaGetSymbolAddress((void**)&Vp, g_V);
    cudaGetSymbolAddress((void**)&Ap, g_A);
    cudaGetSymbolAddress((void**)&hid2, g_hid2);
    cudaGetSymbolAddress((void**)&att2, g_att2);
    cudaGetSymbolAddress((void**)&wq2, g_Wq2);
    cudaGetSymbolAddress((void**)&wk2, g_Wk2);
    cudaGetSymbolAddress((void**)&wv2, g_Wv2);
    cudaGetSymbolAddress((void**)&wo2, g_Wo2);

    const int M = CB * CS;                 // 8192
    const int tot = M * KK;

    cudaFuncSetAttribute(mma_gemm, cudaFuncAttributeMaxDynamicSharedMemorySize,
                         GEMM_SMEM_BYTES);
    cudaFuncSetAttribute(attn_kernel, cudaFuncAttributeMaxDynamicSharedMemorySize,
                         ATTN_SMEM_BYTES);

    // conversions
    cvt_hilo_rows<<<(tot + 255) / 256, 256>>>(hidden, hid2, tot);
    cvt_hilo_T<<<dim3(CHID / 32, KK / 32), dim3(32, 8)>>>(Wq, wq2, CHID);
    cvt_hilo_T<<<dim3((CKV * CD) / 32, KK / 32), dim3(32, 8)>>>(Wk, wk2, CKV * CD);
    cvt_hilo_T<<<dim3((CKV * CD) / 32, KK / 32), dim3(32, 8)>>>(Wv, wv2, CKV * CD);
    cvt_hilo_T<<<dim3(CHID / 32, KK / 32), dim3(32, 8)>>>(Wo, wo2, CHID);

    // QKV projections (tensor cores, split-bf16)
    mma_gemm<<<dim3(CHID / 128, M / 128), 256, GEMM_SMEM_BYTES>>>(hid2, wq2, Qp, M, CHID);
    mma_gemm<<<dim3((CKV * CD) / 128, M / 128), 256, GEMM_SMEM_BYTES>>>(hid2, wk2, Kp, M, CKV * CD);
    mma_gemm<<<dim3((CKV * CD) / 128, M / 128), 256, GEMM_SMEM_BYTES>>>(hid2, wv2, Vp, M, CKV * CD);

    // RoPE
    rope_kernel<<<(CB * CS * CH * 64) / 256, 256>>>(Qp, cosb, sinb, CH, QK_SCALE);
    rope_kernel<<<(CB * CS * CKV * 64) / 256, 256>>>(Kp, cosb, sinb, CKV, 1.0f);

    // attention
    attn_kernel<<<dim3(CNB, CH, CB), 256, ATTN_SMEM_BYTES>>>(Qp, Kp, Vp, amask, Ap);

    // output projection
    cvt_hilo_rows<<<(tot + 255) / 256, 256>>>(Ap, att2, tot);
    mma_gemm<<<dim3(CHID / 128, M / 128), 256, GEMM_SMEM_BYTES>>>(att2, wo2, out, M, CHID);
}

// round 7
// speedup vs baseline: 2.7216x; 1.9694x over previous
#include <cuda_runtime.h>
#include <cuda_fp16.h>
#include <math.h>
#include <stdint.h>

#define CB   2
#define CS   4096
#define CHID 2048
#define CH   16
#define CKV  4
#define CD   128
#define CNB  64
#define NEGV -1000000000.0f
#define QK_SCALE 0.08838834764831845f   // 1/sqrt(128)

#define KK   2048
#define KK2  4096

// -------- scratch (static device memory; allocation-free rule) --------
static __device__ float g_Q[(size_t)CB*CS*CH*CD];          // [B,S,H,D] fp32
static __device__ float g_K[(size_t)CB*CS*CKV*CD];
static __device__ float g_V[(size_t)CB*CS*CKV*CD];
static __device__ float g_A[(size_t)CB*CS*CH*CD];          // attention out fp32
static __device__ __half g_hid2[(size_t)CB*CS*KK2];        // hidden hi|lo [8192,4096]
static __device__ __half g_att2[(size_t)CB*CS*KK2];        // attn   hi|lo [8192,4096]
static __device__ __half g_Wq2[(size_t)CHID*KK];           // [N=2048, K]
static __device__ __half g_Wk2[(size_t)CKV*CD*KK];         // [N=512,  K]
static __device__ __half g_Wv2[(size_t)CKV*CD*KK];
static __device__ __half g_Wo2[(size_t)CHID*KK];

// ============================================================
// portable (non-'a') async-copy / ldmatrix / mma helpers
// ============================================================
__device__ __forceinline__ uint32_t smem_u32(const void* p) {
    uint32_t a;
    asm("{ .reg .u64 t; cvta.to.shared.u64 t, %1; cvt.u32.u64 %0, t; }"
        : "=r"(a) : "l"(p));
    return a;
}
__device__ __forceinline__ void cp16(uint32_t dst, const void* src) {
    asm volatile("cp.async.cg.shared.global [%0], [%1], 16;"
                 :: "r"(dst), "l"(src) : "memory");
}
__device__ __forceinline__ void cp_commit() {
    asm volatile("cp.async.commit_group;" ::: "memory");
}
template<int N_> __device__ __forceinline__ void cp_wait() {
    asm volatile("cp.async.wait_group %0;" :: "n"(N_) : "memory");
}
#define LDSM4(r, addr) \
    asm volatile("ldmatrix.sync.aligned.m8n8.x4.shared.b16 {%0,%1,%2,%3}, [%4];" \
        : "=r"((r)[0]), "=r"((r)[1]), "=r"((r)[2]), "=r"((r)[3]) : "r"(addr))
#define MMA16816(d, a, b0, b1) \
    asm volatile("mma.sync.aligned.m16n8k16.row.col.f32.f16.f16.f32 " \
        "{%0,%1,%2,%3}, {%4,%5,%6,%7}, {%8,%9}, {%0,%1,%2,%3};" \
        : "+f"((d)[0]), "+f"((d)[1]), "+f"((d)[2]), "+f"((d)[3]) \
        : "r"((a)[0]), "r"((a)[1]), "r"((a)[2]), "r"((a)[3]), "r"(b0), "r"(b1))

// ============================================================
// Split-fp16 mma.sync GEMM (2 passes):
//   C[M,N] = Ah@B^T + Al@B^T       (fp32 accum in regs)
// A' [M,2K] fp16 row-major (hi|lo), B' [N,K] fp16 row-major.
// CTA tile 128x128, BK=64, 3-stage cp.async pipeline.
// 8 warps (2x4): warp tile 64(M) x 32(N), m16n8k16.
// ============================================================
#define GSTG    3
#define GSTRIDE 32768                       // bytes per stage (A 16K + B 16K)
#define GEMM_SMEM_BYTES (GSTG * GSTRIDE + 1024)
#define NCHUNK  64                          // 2 passes x 32 chunks of K=64

__global__ __launch_bounds__(256) void mma_gemm(
    const __half* __restrict__ Ab,
    const __half* __restrict__ Bb,
    float* __restrict__ C, int M, int N)
{
    extern __shared__ char dsm_raw[];
    char* dsm = (char*)(((uintptr_t)dsm_raw + 1023) & ~(uintptr_t)1023);
    const uint32_t sb = smem_u32(dsm);

    const int tid  = threadIdx.x;
    const int lane = tid & 31;
    const int w    = tid >> 5;
    const int bx = blockIdx.x * 128;        // N offset
    const int by = blockIdx.y * 128;        // M offset
    const int wm = (w >> 2) * 64;           // warp M offset
    const int wn = (w & 3) * 32;            // warp N offset

    uint32_t aAddr[4];
#pragma unroll
    for (int mt = 0; mt < 4; ++mt) {
        int r = wm + mt * 16 + (lane & 15);
        aAddr[mt] = sb + (uint32_t)r * 128;
    }
    const uint32_t aSw  = (uint32_t)(((wm + (lane & 15)) & 7) << 4);
    const uint32_t aCb0 = (uint32_t)((lane >> 4) * 16);
    uint32_t bAddr[2];
    {
        int n = wn + (lane & 7) + ((lane >> 4) << 3);
        bAddr[0] = sb + 16384 + (uint32_t)n * 128;
        bAddr[1] = bAddr[0] + 16 * 128;
    }
    const uint32_t bSw  = (uint32_t)((((lane & 7) + ((lane >> 4) << 3)) & 7) << 4);
    const uint32_t bCb0 = (uint32_t)(((lane >> 3) & 1) * 16);

    float acc[4][4][4];
#pragma unroll
    for (int mt = 0; mt < 4; ++mt)
#pragma unroll
        for (int nt = 0; nt < 4; ++nt)
#pragma unroll
            for (int e = 0; e < 4; ++e) acc[mt][nt][e] = 0.f;

    auto load_chunk = [&](int c, int stage) {
        const int pass = c >> 5;
        const int k0   = (c & 31) * 64;
        const int aoff = pass * KK;
        const uint32_t sBase = sb + (uint32_t)stage * GSTRIDE;
#pragma unroll
        for (int i = 0; i < 4; ++i) {
            const int id  = tid + i * 256;
            const int row = id >> 3;
            const int ch  = id & 7;
            const uint32_t soff = (uint32_t)row * 128
                                + (uint32_t)((ch * 16) ^ ((row & 7) << 4));
            cp16(sBase + soff,
                 Ab + (size_t)(by + row) * KK2 + aoff + k0 + ch * 8);
            cp16(sBase + 16384 + soff,
                 Bb + (size_t)(bx + row) * KK + k0 + ch * 8);
        }
    };

    load_chunk(0, 0); cp_commit();
    load_chunk(1, 1); cp_commit();

    for (int c = 0; c < NCHUNK; ++c) {
        cp_wait<1>();
        __syncthreads();
        if (c + 2 < NCHUNK) load_chunk(c + 2, (c + 2) % GSTG);
        cp_commit();

        const uint32_t st = (uint32_t)(c % GSTG) * GSTRIDE;
#pragma unroll
        for (int j = 0; j < 4; ++j) {
            const uint32_t akb = ((uint32_t)(j * 32) + aCb0) ^ aSw;
            const uint32_t bkb = ((uint32_t)(j * 32) + bCb0) ^ bSw;
            uint32_t afr[4][4], bfr[2][4];
#pragma unroll
            for (int mt = 0; mt < 4; ++mt)
                LDSM4(afr[mt], aAddr[mt] + st + akb);
#pragma unroll
            for (int ld = 0; ld < 2; ++ld)
                LDSM4(bfr[ld], bAddr[ld] + st + bkb);
#pragma unroll
            for (int mt = 0; mt < 4; ++mt) {
#pragma unroll
                for (int nt = 0; nt < 4; ++nt) {
                    const uint32_t* bf = bfr[nt >> 1];
                    const int p = (nt & 1) * 2;
                    MMA16816(acc[mt][nt], afr[mt], bf[p], bf[p + 1]);
                }
            }
        }
    }

    const int crow = lane >> 2;
    const int ccol = (lane & 3) * 2;
#pragma unroll
    for (int mt = 0; mt < 4; ++mt) {
#pragma unroll
        for (int nt = 0; nt < 4; ++nt) {
            float* cp = C + (size_t)(by + wm + mt * 16 + crow) * N
                          + bx + wn + nt * 8 + ccol;
            *(float2*)cp = make_float2(acc[mt][nt][0], acc[mt][nt][1]);
            *(float2*)(cp + (size_t)8 * N) = make_float2(acc[mt][nt][2], acc[mt][nt][3]);
        }
    }
}

// ============================================================
// fp32 [R,K] -> fp16 hi|lo [R,2K]
// ============================================================
__global__ void cvt_hilo_rows(const float* __restrict__ X,
                              __half* __restrict__ Y, int total)
{
    int idx = blockIdx.x * blockDim.x + threadIdx.x;
    if (idx >= total) return;
    int r = idx >> 11;
    int k = idx & 2047;
    float x = X[idx];
    __half h = __float2half_rn(x);
    float lo = x - __half2float(h);
    Y[(size_t)r * KK2 + k] = h;
    Y[(size_t)r * KK2 + KK + k] = __float2half_rn(lo);
}

// ============================================================
// W fp32 [K,N] -> Y fp16 [N,K] (transpose, no split)
// ============================================================
__global__ void cvt_T_h(const float* __restrict__ W,
                        __half* __restrict__ Y, int N)
{
    __shared__ float t[32][33];
    const int k0 = blockIdx.y * 32, n0 = blockIdx.x * 32;
    const int tx = threadIdx.x, ty = threadIdx.y;   // 32 x 8
#pragma unroll
    for (int j = 0; j < 32; j += 8)
        t[ty + j][tx] = W[(size_t)(k0 + ty + j) * N + n0 + tx];
    __syncthreads();
#pragma unroll
    for (int j = 0; j < 32; j += 8)
        Y[(size_t)(n0 + ty + j) * KK + k0 + tx] = __float2half_rn(t[tx][ty + j]);
}

// ============================================================
// RoPE (in place): X is [B*S, nh, D]; cos/sin are [B*S, D].
// ============================================================
__global__ void rope_kernel(float* __restrict__ X, const float* __restrict__ cs,
                            const float* __restrict__ sn, int nh, float scale)
{
    int idx = blockIdx.x * blockDim.x + threadIdx.x;
    int total = CB * CS * nh * (CD / 2);
    if (idx >= total) return;
    int d = idx & 63;
    int h = (idx >> 6) % nh;
    int t = idx / (64 * nh);
    const float* c = cs + (size_t)t * CD;
    const float* s = sn + (size_t)t * CD;
    float* x = X + ((size_t)t * nh + h) * CD;
    float x1 = x[d], x2 = x[d + 64];
    x[d]      = (x1 * c[d]      - x2 * s[d])      * scale;
    x[d + 64] = (x2 * c[d + 64] + x1 * s[d + 64]) * scale;
}

// ============================================================
// Sparse attention. grid=(NB,H,B), 256 threads.
// Micro-tile: 4 rows (row0..row0+3) x 4 cols (s = tc + 16n).
// Vectorized float4 smem loads for Q/K (QK) and P (PV).
// ============================================================
#define LDK 132                          // K smem row stride (float4-aligned pad)
#define ATTN_SMEM_FLOATS (64*128 + 64*LDK + 64*128 + 64*64 + 4*64)
#define ATTN_SMEM_BYTES  (ATTN_SMEM_FLOATS * 4)

__global__ __launch_bounds__(256) void attn_kernel(
    const float* __restrict__ Q, const float* __restrict__ K,
    const float* __restrict__ V, const float* __restrict__ am,
    float* __restrict__ Aout)
{
    extern __shared__ float smem[];
    float* Qs  = smem;                   // [64][128]
    float* Ks  = Qs  + 64 * 128;         // [64][LDK]
    float* Vs  = Ks  + 64 * LDK;         // [64][128]
    float* Ps  = Vs  + 64 * 128;         // [64][64]
    float* m_s = Ps  + 64 * 64;
    float* l_s = m_s + 64;
    float* a_s = l_s + 64;
    float* km_s= a_s + 64;

    const int i = blockIdx.x, h = blockIdx.y, b = blockIdx.z;
    const int kvh = h >> 2;
    const int tid = threadIdx.x;
    const int tr  = tid >> 4;
    const int tc  = tid & 15;
    const int row0 = tr * 4;

    const float* qg = Q + (((size_t)b * CS + (size_t)i * 64) * CH + h) * CD;
    for (int e = tid; e < 64 * 32; e += 256) {
        int t = e >> 5, d4 = (e & 31) << 2;
        *(float4*)(Qs + t * 128 + d4) = *(const float4*)(qg + (size_t)t * CH * CD + d4);
    }
    if (tid < 64) { m_s[tid] = -3.0e38f; l_s[tid] = 0.f; }

    float O[4][8];
#pragma unroll
    for (int j = 0; j < 4; j++)
#pragma unroll
        for (int n = 0; n < 8; n++) O[j][n] = 0.f;

    __syncthreads();

    for (int c = 0; c < 8; c++) {
        int kb; bool intra = false; bool valid;
        if (c < 4) {
            kb = i - 3 + c;
            valid = (kb >= 0);
            intra = (c == 3);
        } else {
            int lo = (i > 32) ? (i - 32) : 0;
            int cnt = (i - lo + 3) >> 2;
            int j = cnt - 8 + c;
            valid = (i >= 1) && (j >= 0);
            kb = lo + 4 * j;
        }
        if (!valid) continue;

        const float* kg = K + (((size_t)b * CS + (size_t)kb * 64) * CKV + kvh) * CD;
        const float* vg = V + (((size_t)b * CS + (size_t)kb * 64) * CKV + kvh) * CD;
        for (int e = tid; e < 64 * 32; e += 256) {
            int t = e >> 5, d4 = (e & 31) << 2;
            *(float4*)(Ks + t * LDK + d4) = *(const float4*)(kg + (size_t)t * CKV * CD + d4);
            *(float4*)(Vs + t * 128 + d4) = *(const float4*)(vg + (size_t)t * CKV * CD + d4);
        }
        if (tid < 64) km_s[tid] = am[(size_t)b * CS + (size_t)kb * 64 + tid];
        __syncthreads();

        // ---- scores: rows row0..+3, cols s = tc + 16n ----
        float acc[4][4];
#pragma unroll
        for (int j = 0; j < 4; j++)
#pragma unroll
            for (int n = 0; n < 4; n++) acc[j][n] = 0.f;
        const float* qp = Qs + row0 * 128;
        const float* kp = Ks + tc * LDK;
#pragma unroll 2
        for (int d = 0; d < 128; d += 4) {
            float4 qv[4], kv[4];
#pragma unroll
            for (int j = 0; j < 4; j++) qv[j] = *(const float4*)(qp + j * 128 + d);
#pragma unroll
            for (int n = 0; n < 4; n++) kv[n] = *(const float4*)(kp + n * 16 * LDK + d);
#pragma unroll
            for (int j = 0; j < 4; j++)
#pragma unroll
                for (int n = 0; n < 4; n++) {
                    acc[j][n] = fmaf(qv[j].x, kv[n].x, acc[j][n]);
                    acc[j][n] = fmaf(qv[j].y, kv[n].y, acc[j][n]);
                    acc[j][n] = fmaf(qv[j].z, kv[n].z, acc[j][n]);
                    acc[j][n] = fmaf(qv[j].w, kv[n].w, acc[j][n]);
                }
        }

        // ---- mask + online softmax ----
#pragma unroll
        for (int j = 0; j < 4; j++) {
            int t = row0 + j;
#pragma unroll
            for (int n = 0; n < 4; n++) {
                int s = tc + 16 * n;
                float km = km_s[s];
                acc[j][n] += (1.0f - km) * NEGV;
                if (intra && s > t) acc[j][n] += NEGV;
            }
            float mx = fmaxf(fmaxf(acc[j][0], acc[j][1]), fmaxf(acc[j][2], acc[j][3]));
#pragma unroll
            for (int o = 1; o < 16; o <<= 1)
                mx = fmaxf(mx, __shfl_xor_sync(0xffffffffu, mx, o));
            float mo = m_s[t];
            float mn = fmaxf(mo, mx);
            float p[4], ps = 0.f;
#pragma unroll
            for (int n = 0; n < 4; n++) { p[n] = __expf(acc[j][n] - mn); ps += p[n]; }
#pragma unroll
            for (int o = 1; o < 16; o <<= 1)
                ps += __shfl_xor_sync(0xffffffffu, ps, o);
            if (tc == 0) {
                float al = __expf(mo - mn);
                a_s[t] = al;
                l_s[t] = l_s[t] * al + ps;
                m_s[t] = mn;
            }
#pragma unroll
            for (int n = 0; n < 4; n++)
                Ps[t * 64 + tc + 16 * n] = p[n];
        }
        __syncwarp();

        // ---- O = O*alpha + P @ V ----
        float alpha[4];
#pragma unroll
        for (int j = 0; j < 4; j++) alpha[j] = a_s[row0 + j];
#pragma unroll
        for (int j = 0; j < 4; j++)
#pragma unroll
            for (int n = 0; n < 8; n++) O[j][n] *= alpha[j];

        const float* pp = Ps + row0 * 64;
        const float* vp = Vs + tc * 8;
#pragma unroll 2
        for (int s = 0; s < 64; s += 4) {
            float4 pr[4];
#pragma unroll
            for (int j = 0; j < 4; j++) pr[j] = *(const float4*)(pp + j * 64 + s);
#pragma unroll
            for (int u = 0; u < 4; u++) {
                float4 va = *(const float4*)(vp + (s + u) * 128);
                float4 vb = *(const float4*)(vp + (s + u) * 128 + 4);
                float vv[8] = {va.x, va.y, va.z, va.w, vb.x, vb.y, vb.z, vb.w};
#pragma unroll
                for (int j = 0; j < 4; j++) {
                    float pj = (u == 0) ? pr[j].x : (u == 1) ? pr[j].y
                             : (u == 2) ? pr[j].z : pr[j].w;
#pragma unroll
                    for (int n = 0; n < 8; n++)
                        O[j][n] = fmaf(pj, vv[n], O[j][n]);
                }
            }
        }
        __syncthreads();
    }

    float* og = Aout + (((size_t)b * CS + (size_t)i * 64) * CH + h) * CD;
#pragma unroll
    for (int j = 0; j < 4; j++) {
        float linv = 1.0f / l_s[row0 + j];
        float* orow = og + (size_t)(row0 + j) * CH * CD + tc * 8;
        float4 va = make_float4(O[j][0]*linv, O[j][1]*linv, O[j][2]*linv, O[j][3]*linv);
        float4 vb = make_float4(O[j][4]*linv, O[j][5]*linv, O[j][6]*linv, O[j][7]*linv);
        *(float4*)(orow) = va;
        *(float4*)(orow + 4) = vb;
    }
}

// ============================================================
// launcher
// ============================================================
extern "C" void kernel_launch(void* const* d_in, const int* in_sizes, int n_in,
                              void* d_out, int out_size)
{
    (void)in_sizes; (void)n_in; (void)out_size;
    const float* hidden = (const float*)d_in[0];
    const float* cosb   = (const float*)d_in[1];
    const float* sinb   = (const float*)d_in[2];
    const float* amask  = (const float*)d_in[3];
    const float* Wq     = (const float*)d_in[4];
    const float* Wk     = (const float*)d_in[5];
    const float* Wv     = (const float*)d_in[6];
    const float* Wo     = (const float*)d_in[7];
    float* out = (float*)d_out;

    float *Qp, *Kp, *Vp, *Ap;
    __half *hid2, *att2, *wq2, *wk2, *wv2, *wo2;
    cudaGetSymbolAddress((void**)&Qp, g_Q);
    cudaGetSymbolAddress((void**)&Kp, g_K);
    cudaGetSymbolAddress((void**)&Vp, g_V);
    cudaGetSymbolAddress((void**)&Ap, g_A);
    cudaGetSymbolAddress((void**)&hid2, g_hid2);
    cudaGetSymbolAddress((void**)&att2, g_att2);
    cudaGetSymbolAddress((void**)&wq2, g_Wq2);
    cudaGetSymbolAddress((void**)&wk2, g_Wk2);
    cudaGetSymbolAddress((void**)&wv2, g_Wv2);
    cudaGetSymbolAddress((void**)&wo2, g_Wo2);

    const int M = CB * CS;                 // 8192
    const int tot = M * KK;

    cudaFuncSetAttribute(mma_gemm, cudaFuncAttributeMaxDynamicSharedMemorySize,
                         GEMM_SMEM_BYTES);
    cudaFuncSetAttribute(attn_kernel, cudaFuncAttributeMaxDynamicSharedMemorySize,
                         ATTN_SMEM_BYTES);

    // conversions
    cvt_hilo_rows<<<(tot + 255) / 256, 256>>>(hidden, hid2, tot);
    cvt_T_h<<<dim3(CHID / 32, KK / 32), dim3(32, 8)>>>(Wq, wq2, CHID);
    cvt_T_h<<<dim3((CKV * CD) / 32, KK / 32), dim3(32, 8)>>>(Wk, wk2, CKV * CD);
    cvt_T_h<<<dim3((CKV * CD) / 32, KK / 32), dim3(32, 8)>>>(Wv, wv2, CKV * CD);
    cvt_T_h<<<dim3(CHID / 32, KK / 32), dim3(32, 8)>>>(Wo, wo2, CHID);

    // QKV projections (tensor cores, split-fp16 2-pass)
    mma_gemm<<<dim3(CHID / 128, M / 128), 256, GEMM_SMEM_BYTES>>>(hid2, wq2, Qp, M, CHID);
    mma_gemm<<<dim3((CKV * CD) / 128, M / 128), 256, GEMM_SMEM_BYTES>>>(hid2, wk2, Kp, M, CKV * CD);
    mma_gemm<<<dim3((CKV * CD) / 128, M / 128), 256, GEMM_SMEM_BYTES>>>(hid2, wv2, Vp, M, CKV * CD);

    // RoPE
    rope_kernel<<<(CB * CS * CH * 64) / 256, 256>>>(Qp, cosb, sinb, CH, QK_SCALE);
    rope_kernel<<<(CB * CS * CKV * 64) / 256, 256>>>(Kp, cosb, sinb, CKV, 1.0f);

    // attention
    attn_kernel<<<dim3(CNB, CH, CB), 256, ATTN_SMEM_BYTES>>>(Qp, Kp, Vp, amask, Ap);

    // output projection
    cvt_hilo_rows<<<(tot + 255) / 256, 256>>>(Ap, att2, tot);
    mma_gemm<<<dim3(CHID / 128, M / 128), 256, GEMM_SMEM_BYTES>>>(att2, wo2, out, M, CHID);
}

// round 9
// speedup vs baseline: 4.4124x; 1.6212x over previous
#include <cuda_runtime.h>
#include <cuda_fp16.h>
#include <math.h>
#include <stdint.h>

#define CB   2
#define CS   4096
#define CHID 2048
#define CH   16
#define CKV  4
#define CD   128
#define CNB  64
#define NEGV -1000000000.0f
#define QK_SCALE 0.08838834764831845f   // 1/sqrt(128)

#define KK   2048
#define KK2  4096

// -------- scratch (static device memory; allocation-free rule) --------
static __device__ float g_Q[(size_t)CB*CS*CH*CD];          // QKV GEMM outs fp32
static __device__ float g_K[(size_t)CB*CS*CKV*CD];
static __device__ float g_V[(size_t)CB*CS*CKV*CD];
static __device__ float g_A[(size_t)CB*CS*CH*CD];          // attention out fp32
static __device__ __half g_hid2[(size_t)CB*CS*KK2];        // hidden hi|lo
static __device__ __half g_att2[(size_t)CB*CS*KK2];        // attn   hi|lo
static __device__ __half g_Wq2[(size_t)CHID*KK];
static __device__ __half g_Wk2[(size_t)CKV*CD*KK];
static __device__ __half g_Wv2[(size_t)CKV*CD*KK];
static __device__ __half g_Wo2[(size_t)CHID*KK];
// fp16 hi/lo attention operands
static __device__ __half g_Qh[(size_t)CB*CS*CH*CD];
static __device__ __half g_Ql[(size_t)CB*CS*CH*CD];
static __device__ __half g_Kh[(size_t)CB*CS*CKV*CD];
static __device__ __half g_Kl[(size_t)CB*CS*CKV*CD];
static __device__ __half g_Vh[(size_t)CB*CS*CKV*CD];
static __device__ __half g_Vl[(size_t)CB*CS*CKV*CD];

// ============================================================
// portable async-copy / ldmatrix / mma helpers
// ============================================================
__device__ __forceinline__ uint32_t smem_u32(const void* p) {
    uint32_t a;
    asm("{ .reg .u64 t; cvta.to.shared.u64 t, %1; cvt.u32.u64 %0, t; }"
        : "=r"(a) : "l"(p));
    return a;
}
__device__ __forceinline__ void cp16(uint32_t dst, const void* src) {
    asm volatile("cp.async.cg.shared.global [%0], [%1], 16;"
                 :: "r"(dst), "l"(src) : "memory");
}
__device__ __forceinline__ void cp_commit() {
    asm volatile("cp.async.commit_group;" ::: "memory");
}
template<int N_> __device__ __forceinline__ void cp_wait() {
    asm volatile("cp.async.wait_group %0;" :: "n"(N_) : "memory");
}
__device__ __forceinline__ void bar_g(int id) {
    asm volatile("bar.sync %0, 128;" :: "r"(id) : "memory");
}
#define LDSM4(r, addr) \
    asm volatile("ldmatrix.sync.aligned.m8n8.x4.shared.b16 {%0,%1,%2,%3}, [%4];" \
        : "=r"((r)[0]), "=r"((r)[1]), "=r"((r)[2]), "=r"((r)[3]) : "r"(addr))
#define LDSM4T(r, addr) \
    asm volatile("ldmatrix.sync.aligned.m8n8.x4.trans.shared.b16 {%0,%1,%2,%3}, [%4];" \
        : "=r"((r)[0]), "=r"((r)[1]), "=r"((r)[2]), "=r"((r)[3]) : "r"(addr))
#define MMA16816(d, a, b0, b1) \
    asm volatile("mma.sync.aligned.m16n8k16.row.col.f32.f16.f16.f32 " \
        "{%0,%1,%2,%3}, {%4,%5,%6,%7}, {%8,%9}, {%0,%1,%2,%3};" \
        : "+f"((d)[0]), "+f"((d)[1]), "+f"((d)[2]), "+f"((d)[3]) \
        : "r"((a)[0]), "r"((a)[1]), "r"((a)[2]), "r"((a)[3]), "r"(b0), "r"(b1))

__device__ __forceinline__ uint32_t packh2(__half a, __half b) {
    __half2 t = __halves2half2(a, b);
    return *reinterpret_cast<uint32_t*>(&t);
}

// ============================================================
// Split-fp16 mma.sync GEMM (unchanged from R7, passing)
// ============================================================
#define GSTG    3
#define GSTRIDE 32768
#define GEMM_SMEM_BYTES (GSTG * GSTRIDE + 1024)
#define NCHUNK  64

__global__ __launch_bounds__(256) void mma_gemm(
    const __half* __restrict__ Ab,
    const __half* __restrict__ Bb,
    float* __restrict__ C, int M, int N)
{
    extern __shared__ char dsm_raw[];
    char* dsm = (char*)(((uintptr_t)dsm_raw + 1023) & ~(uintptr_t)1023);
    const uint32_t sb = smem_u32(dsm);

    const int tid  = threadIdx.x;
    const int lane = tid & 31;
    const int w    = tid >> 5;
    const int bx = blockIdx.x * 128;
    const int by = blockIdx.y * 128;
    const int wm = (w >> 2) * 64;
    const int wn = (w & 3) * 32;

    uint32_t aAddr[4];
#pragma unroll
    for (int mt = 0; mt < 4; ++mt) {
        int r = wm + mt * 16 + (lane & 15);
        aAddr[mt] = sb + (uint32_t)r * 128;
    }
    const uint32_t aSw  = (uint32_t)(((wm + (lane & 15)) & 7) << 4);
    const uint32_t aCb0 = (uint32_t)((lane >> 4) * 16);
    uint32_t bAddr[2];
    {
        int n = wn + (lane & 7) + ((lane >> 4) << 3);
        bAddr[0] = sb + 16384 + (uint32_t)n * 128;
        bAddr[1] = bAddr[0] + 16 * 128;
    }
    const uint32_t bSw  = (uint32_t)((((lane & 7) + ((lane >> 4) << 3)) & 7) << 4);
    const uint32_t bCb0 = (uint32_t)(((lane >> 3) & 1) * 16);

    float acc[4][4][4];
#pragma unroll
    for (int mt = 0; mt < 4; ++mt)
#pragma unroll
        for (int nt = 0; nt < 4; ++nt)
#pragma unroll
            for (int e = 0; e < 4; ++e) acc[mt][nt][e] = 0.f;

    auto load_chunk = [&](int c, int stage) {
        const int pass = c >> 5;
        const int k0   = (c & 31) * 64;
        const int aoff = pass * KK;
        const uint32_t sBase = sb + (uint32_t)stage * GSTRIDE;
#pragma unroll
        for (int i = 0; i < 4; ++i) {
            const int id  = tid + i * 256;
            const int row = id >> 3;
            const int ch  = id & 7;
            const uint32_t soff = (uint32_t)row * 128
                                + (uint32_t)((ch * 16) ^ ((row & 7) << 4));
            cp16(sBase + soff,
                 Ab + (size_t)(by + row) * KK2 + aoff + k0 + ch * 8);
            cp16(sBase + 16384 + soff,
                 Bb + (size_t)(bx + row) * KK + k0 + ch * 8);
        }
    };

    load_chunk(0, 0); cp_commit();
    load_chunk(1, 1); cp_commit();

    for (int c = 0; c < NCHUNK; ++c) {
        cp_wait<1>();
        __syncthreads();
        if (c + 2 < NCHUNK) load_chunk(c + 2, (c + 2) % GSTG);
        cp_commit();

        const uint32_t st = (uint32_t)(c % GSTG) * GSTRIDE;
#pragma unroll
        for (int j = 0; j < 4; ++j) {
            const uint32_t akb = ((uint32_t)(j * 32) + aCb0) ^ aSw;
            const uint32_t bkb = ((uint32_t)(j * 32) + bCb0) ^ bSw;
            uint32_t afr[4][4], bfr[2][4];
#pragma unroll
            for (int mt = 0; mt < 4; ++mt)
                LDSM4(afr[mt], aAddr[mt] + st + akb);
#pragma unroll
            for (int ld = 0; ld < 2; ++ld)
                LDSM4(bfr[ld], bAddr[ld] + st + bkb);
#pragma unroll
            for (int mt = 0; mt < 4; ++mt) {
#pragma unroll
                for (int nt = 0; nt < 4; ++nt) {
                    const uint32_t* bf = bfr[nt >> 1];
                    const int p = (nt & 1) * 2;
                    MMA16816(acc[mt][nt], afr[mt], bf[p], bf[p + 1]);
                }
            }
        }
    }

    const int crow = lane >> 2;
    const int ccol = (lane & 3) * 2;
#pragma unroll
    for (int mt = 0; mt < 4; ++mt) {
#pragma unroll
        for (int nt = 0; nt < 4; ++nt) {
            float* cp = C + (size_t)(by + wm + mt * 16 + crow) * N
                          + bx + wn + nt * 8 + ccol;
            *(float2*)cp = make_float2(acc[mt][nt][0], acc[mt][nt][1]);
            *(float2*)(cp + (size_t)8 * N) = make_float2(acc[mt][nt][2], acc[mt][nt][3]);
        }
    }
}

// ============================================================
// conversion kernels
// ============================================================
__global__ void cvt_hilo_rows(const float* __restrict__ X,
                              __half* __restrict__ Y, int total)
{
    int idx = blockIdx.x * blockDim.x + threadIdx.x;
    if (idx >= total) return;
    int r = idx >> 11;
    int k = idx & 2047;
    float x = X[idx];
    __half h = __float2half_rn(x);
    float lo = x - __half2float(h);
    Y[(size_t)r * KK2 + k] = h;
    Y[(size_t)r * KK2 + KK + k] = __float2half_rn(lo);
}

__global__ void cvt_T_h(const float* __restrict__ W,
                        __half* __restrict__ Y, int N)
{
    __shared__ float t[32][33];
    const int k0 = blockIdx.y * 32, n0 = blockIdx.x * 32;
    const int tx = threadIdx.x, ty = threadIdx.y;
#pragma unroll
    for (int j = 0; j < 32; j += 8)
        t[ty + j][tx] = W[(size_t)(k0 + ty + j) * N + n0 + tx];
    __syncthreads();
#pragma unroll
    for (int j = 0; j < 32; j += 8)
        Y[(size_t)(n0 + ty + j) * KK + k0 + tx] = __float2half_rn(t[tx][ty + j]);
}

// RoPE + hi/lo split: X fp32 [B*S, nh, D] -> Yh/Yl fp16
__global__ void rope_split(const float* __restrict__ X,
                           const float* __restrict__ cs, const float* __restrict__ sn,
                           __half* __restrict__ Yh, __half* __restrict__ Yl,
                           int nh, float scale)
{
    int idx = blockIdx.x * blockDim.x + threadIdx.x;
    int total = CB * CS * nh * (CD / 2);
    if (idx >= total) return;
    int d = idx & 63;
    int h = (idx >> 6) % nh;
    int t = idx / (64 * nh);
    const float* c = cs + (size_t)t * CD;
    const float* s = sn + (size_t)t * CD;
    const float* x = X + ((size_t)t * nh + h) * CD;
    size_t o = ((size_t)t * nh + h) * CD;
    float x1 = x[d], x2 = x[d + 64];
    float v1 = (x1 * c[d]      - x2 * s[d])      * scale;
    float v2 = (x2 * c[d + 64] + x1 * s[d + 64]) * scale;
    __half h1 = __float2half_rn(v1), h2 = __float2half_rn(v2);
    Yh[o + d] = h1;      Yl[o + d] = __float2half_rn(v1 - __half2float(h1));
    Yh[o + d + 64] = h2; Yl[o + d + 64] = __float2half_rn(v2 - __half2float(h2));
}

__global__ void cvt_split(const float* __restrict__ X,
                          __half* __restrict__ Yh, __half* __restrict__ Yl, int total)
{
    int idx = blockIdx.x * blockDim.x + threadIdx.x;
    if (idx >= total) return;
    float x = X[idx];
    __half h = __float2half_rn(x);
    Yh[idx] = h;
    Yl[idx] = __float2half_rn(x - __half2float(h));
}

// ============================================================
// Tensor-core sparse attention. grid=(NB,H,B), 256 threads.
// Warps 0-3 (group 0): local chunks; warps 4-7 (group 1): global.
// Split-softmax merge at end. 3-pass hi/lo splits everywhere.
// smem: Qh,Ql (32K) + per-group {Kh,Kl,Vh,Vl} (64K each) = 160K.
// ============================================================
#define AT_SMEM_BYTES (163840 + 1024)

__device__ __forceinline__ uint32_t soff256(int row, uint32_t ch) {
    return (uint32_t)row * 256 + ((ch ^ (uint32_t)(row & 7)) << 4);
}

__global__ __launch_bounds__(256) void attn_mma(
    const __half* __restrict__ Qh_, const __half* __restrict__ Ql_,
    const __half* __restrict__ Kh_, const __half* __restrict__ Kl_,
    const __half* __restrict__ Vh_, const __half* __restrict__ Vl_,
    const float* __restrict__ am, float* __restrict__ Aout)
{
    extern __shared__ char dsm_raw[];
    char* dsm = (char*)(((uintptr_t)dsm_raw + 1023) & ~(uintptr_t)1023);
    __shared__ float sM[2][64], sL[2][64], sKM[2][64];

    const int i = blockIdx.x, h = blockIdx.y, b = blockIdx.z;
    const int kvh = h >> 2;
    const int tid = threadIdx.x, lane = tid & 31, wid = tid >> 5;
    const int g = wid >> 2, w4 = wid & 3, wrow = w4 * 16;
    const int gtid = tid & 127;

    const uint32_t sQh = smem_u32(dsm);
    const uint32_t sQl = sQh + 16384;
    const uint32_t sKh = sQh + 32768 + (uint32_t)g * 65536;
    const uint32_t sKl = sKh + 16384;
    const uint32_t sVh = sKh + 32768;
    const uint32_t sVl = sKh + 49152;
    float* smO = (float*)(dsm + 32768);     // merge buffer (overlays group-0 K/V)

    // ---- Q tile cp.async (all threads) ----
    const __half* qhg = Qh_ + (((size_t)b * CS + (size_t)i * 64) * CH + h) * CD;
    const __half* qlg = Ql_ + (((size_t)b * CS + (size_t)i * 64) * CH + h) * CD;
    for (int e = tid; e < 1024; e += 256) {
        int row = e >> 4; uint32_t ch = (uint32_t)(e & 15);
        uint32_t off = soff256(row, ch);
        cp16(sQh + off, qhg + (size_t)row * CH * CD + ch * 8);
        cp16(sQl + off, qlg + (size_t)row * CH * CD + ch * 8);
    }

    // chunk descriptor
    auto chunk_info = [&](int ci, int& kb, bool& intra) -> bool {
        if (g == 0) {
            kb = i - 3 + ci;
            intra = (ci == 3);
            return kb >= 0;
        } else {
            intra = false;
            int lo = (i > 32) ? (i - 32) : 0;
            int cnt = (i - lo + 3) >> 2;
            int j = cnt - 4 + ci;
            kb = lo + 4 * j;
            return (i >= 1) && (j >= 0);
        }
    };

    auto load_kv = [&](int kb) {
        const size_t base = (((size_t)b * CS + (size_t)kb * 64) * CKV + kvh) * CD;
        for (int e = gtid; e < 1024; e += 128) {
            int row = e >> 4; uint32_t ch = (uint32_t)(e & 15);
            uint32_t off = soff256(row, ch);
            size_t so = base + (size_t)row * CKV * CD + ch * 8;
            cp16(sKh + off, Kh_ + so);
            cp16(sKl + off, Kl_ + so);
            cp16(sVh + off, Vh_ + so);
            cp16(sVl + off, Vl_ + so);
        }
        if (gtid < 64) sKM[g][gtid] = am[(size_t)b * CS + (size_t)kb * 64 + gtid];
    };

    float O[16][4];
#pragma unroll
    for (int nt = 0; nt < 16; ++nt)
#pragma unroll
        for (int e = 0; e < 4; ++e) O[nt][e] = 0.f;
    float m0 = -1e30f, l0 = 0.f, m1 = -1e30f, l1 = 0.f;

    const int rl = lane >> 2;
    const int row0 = wrow + rl, row1 = row0 + 8;

    // preload chunk 0
    {
        int kb; bool intra;
        if (chunk_info(0, kb, intra)) load_kv(kb);
    }
    cp_commit(); cp_wait<0>();
    __syncthreads();

    for (int ci = 0; ci < 4; ++ci) {
        int kb; bool intra;
        bool valid = chunk_info(ci, kb, intra);
        if (ci > 0) {
            bar_g(g + 1);
            if (valid) load_kv(kb);
            cp_commit(); cp_wait<0>();
            bar_g(g + 1);
        }
        if (!valid) continue;

        // ---- S = Qh*Kh + Ql*Kh + Qh*Kl ----
        float S[8][4];
#pragma unroll
        for (int nt = 0; nt < 8; ++nt)
#pragma unroll
            for (int e = 0; e < 4; ++e) S[nt][e] = 0.f;

#pragma unroll
        for (int ks = 0; ks < 8; ++ks) {
            int qrow = wrow + (lane & 15);
            uint32_t qoff = soff256(qrow, (uint32_t)(2 * ks + (lane >> 4)));
            uint32_t qh[4], ql[4];
            LDSM4(qh, sQh + qoff);
            LDSM4(ql, sQl + qoff);
#pragma unroll
            for (int nt2 = 0; nt2 < 4; ++nt2) {
                int n = nt2 * 16 + (lane & 7) + ((lane >> 4) << 3);
                uint32_t koff = soff256(n, (uint32_t)(2 * ks + ((lane >> 3) & 1)));
                uint32_t bh[4], bl[4];
                LDSM4(bh, sKh + koff);
                MMA16816(S[nt2 * 2],     qh, bh[0], bh[1]);
                MMA16816(S[nt2 * 2 + 1], qh, bh[2], bh[3]);
                MMA16816(S[nt2 * 2],     ql, bh[0], bh[1]);
                MMA16816(S[nt2 * 2 + 1], ql, bh[2], bh[3]);
                LDSM4(bl, sKl + koff);
                MMA16816(S[nt2 * 2],     qh, bl[0], bl[1]);
                MMA16816(S[nt2 * 2 + 1], qh, bl[2], bl[3]);
            }
        }

        // ---- mask ----
#pragma unroll
        for (int nt = 0; nt < 8; ++nt) {
            int c0 = nt * 8 + 2 * (lane & 3);
            float km0 = sKM[g][c0], km1 = sKM[g][c0 + 1];
            S[nt][0] += (1.0f - km0) * NEGV;
            S[nt][1] += (1.0f - km1) * NEGV;
            S[nt][2] += (1.0f - km0) * NEGV;
            S[nt][3] += (1.0f - km1) * NEGV;
            if (intra) {
                if (c0 > row0)     S[nt][0] += NEGV;
                if (c0 + 1 > row0) S[nt][1] += NEGV;
                if (c0 > row1)     S[nt][2] += NEGV;
                if (c0 + 1 > row1) S[nt][3] += NEGV;
            }
        }

        // ---- online softmax (rows row0, row1; 4 lanes per row) ----
        float mx0 = -1e30f, mx1 = -1e30f;
#pragma unroll
        for (int nt = 0; nt < 8; ++nt) {
            mx0 = fmaxf(mx0, fmaxf(S[nt][0], S[nt][1]));
            mx1 = fmaxf(mx1, fmaxf(S[nt][2], S[nt][3]));
        }
#pragma unroll
        for (int o = 1; o < 4; o <<= 1) {
            mx0 = fmaxf(mx0, __shfl_xor_sync(0xffffffffu, mx0, o));
            mx1 = fmaxf(mx1, __shfl_xor_sync(0xffffffffu, mx1, o));
        }
        float mn0 = fmaxf(m0, mx0), mn1 = fmaxf(m1, mx1);
        float a0 = __expf(m0 - mn0), a1 = __expf(m1 - mn1);
        float s0 = 0.f, s1 = 0.f;
#pragma unroll
        for (int nt = 0; nt < 8; ++nt) {
            S[nt][0] = __expf(S[nt][0] - mn0);
            S[nt][1] = __expf(S[nt][1] - mn0);
            S[nt][2] = __expf(S[nt][2] - mn1);
            S[nt][3] = __expf(S[nt][3] - mn1);
            s0 += S[nt][0] + S[nt][1];
            s1 += S[nt][2] + S[nt][3];
        }
#pragma unroll
        for (int o = 1; o < 4; o <<= 1) {
            s0 += __shfl_xor_sync(0xffffffffu, s0, o);
            s1 += __shfl_xor_sync(0xffffffffu, s1, o);
        }
        l0 = l0 * a0 + s0;
        l1 = l1 * a1 + s1;
        m0 = mn0; m1 = mn1;
#pragma unroll
        for (int nt = 0; nt < 16; ++nt) {
            O[nt][0] *= a0; O[nt][1] *= a0;
            O[nt][2] *= a1; O[nt][3] *= a1;
        }

        // ---- O += Ph*Vh + Pl*Vh + Ph*Vl ----
#pragma unroll
        for (int kt = 0; kt < 4; ++kt) {
            uint32_t ph[4], pl[4];
#pragma unroll
            for (int jj = 0; jj < 2; ++jj) {
                int t_ = 2 * kt + jj;
                __half h0 = __float2half_rn(S[t_][0]);
                __half h1 = __float2half_rn(S[t_][1]);
                __half h2 = __float2half_rn(S[t_][2]);
                __half h3 = __float2half_rn(S[t_][3]);
                __half e0 = __float2half_rn(S[t_][0] - __half2float(h0));
                __half e1 = __float2half_rn(S[t_][1] - __half2float(h1));
                __half e2 = __float2half_rn(S[t_][2] - __half2float(h2));
                __half e3 = __float2half_rn(S[t_][3] - __half2float(h3));
                ph[jj * 2]     = packh2(h0, h1);
                ph[jj * 2 + 1] = packh2(h2, h3);
                pl[jj * 2]     = packh2(e0, e1);
                pl[jj * 2 + 1] = packh2(e2, e3);
            }
            // a-frag order: a0=tile2kt(rows rl), a1=tile2kt(rows rl+8), a2/a3=tile2kt+1
            uint32_t pA[4] = { ph[0], ph[1], ph[2], ph[3] };
            uint32_t pB[4] = { pl[0], pl[1], pl[2], pl[3] };
            int key = 16 * kt + (lane & 15);
#pragma unroll
            for (int nd2 = 0; nd2 < 8; ++nd2) {
                uint32_t voff = soff256(key, (uint32_t)(2 * nd2 + (lane >> 4)));
                uint32_t vh[4], vl[4];
                LDSM4T(vh, sVh + voff);
                MMA16816(O[nd2 * 2],     pA, vh[0], vh[1]);
                MMA16816(O[nd2 * 2 + 1], pA, vh[2], vh[3]);
                MMA16816(O[nd2 * 2],     pB, vh[0], vh[1]);
                MMA16816(O[nd2 * 2 + 1], pB, vh[2], vh[3]);
                LDSM4T(vl, sVl + voff);
                MMA16816(O[nd2 * 2],     pA, vl[0], vl[1]);
                MMA16816(O[nd2 * 2 + 1], pA, vl[2], vl[3]);
            }
        }
    }

    // ---- split-softmax merge ----
    __syncthreads();
    if ((lane & 3) == 0) {
        sM[g][row0] = m0; sL[g][row0] = l0;
        sM[g][row1] = m1; sL[g][row1] = l1;
    }
    __syncthreads();
    float mA0 = sM[0][row0], mB0 = sM[1][row0];
    float mA1 = sM[0][row1], mB1 = sM[1][row1];
    float mt0 = fmaxf(mA0, mB0), mt1 = fmaxf(mA1, mB1);
    float fA0 = __expf(mA0 - mt0), fB0 = __expf(mB0 - mt0);
    float fA1 = __expf(mA1 - mt1), fB1 = __expf(mB1 - mt1);
    float den0 = sL[0][row0] * fA0 + sL[1][row0] * fB0;
    float den1 = sL[0][row1] * fA1 + sL[1][row1] * fB1;

    if (g == 1) {
#pragma unroll
        for (int nt = 0; nt < 16; ++nt) {
            int c0 = nt * 8 + 2 * (lane & 3);
            smO[row0 * 128 + c0]     = O[nt][0] * fB0;
            smO[row0 * 128 + c0 + 1] = O[nt][1] * fB0;
            smO[row1 * 128 + c0]     = O[nt][2] * fB1;
            smO[row1 * 128 + c0 + 1] = O[nt][3] * fB1;
        }
    }
    __syncthreads();
    if (g == 0) {
        float* og = Aout + (((size_t)b * CS + (size_t)i * 64) * CH + h) * CD;
        float r0 = 1.0f / den0, r1 = 1.0f / den1;
#pragma unroll
        for (int nt = 0; nt < 16; ++nt) {
            int c0 = nt * 8 + 2 * (lane & 3);
            float o00 = (O[nt][0] * fA0 + smO[row0 * 128 + c0])     * r0;
            float o01 = (O[nt][1] * fA0 + smO[row0 * 128 + c0 + 1]) * r0;
            float o10 = (O[nt][2] * fA1 + smO[row1 * 128 + c0])     * r1;
            float o11 = (O[nt][3] * fA1 + smO[row1 * 128 + c0 + 1]) * r1;
            *(float2*)(og + (size_t)row0 * CH * CD + c0) = make_float2(o00, o01);
            *(float2*)(og + (size_t)row1 * CH * CD + c0) = make_float2(o10, o11);
        }
    }
}

// ============================================================
// launcher
// ============================================================
extern "C" void kernel_launch(void* const* d_in, const int* in_sizes, int n_in,
                              void* d_out, int out_size)
{
    (void)in_sizes; (void)n_in; (void)out_size;
    const float* hidden = (const float*)d_in[0];
    const float* cosb   = (const float*)d_in[1];
    const float* sinb   = (const float*)d_in[2];
    const float* amask  = (const float*)d_in[3];
    const float* Wq     = (const float*)d_in[4];
    const float* Wk     = (const float*)d_in[5];
    const float* Wv     = (const float*)d_in[6];
    const float* Wo     = (const float*)d_in[7];
    float* out = (float*)d_out;

    float *Qp, *Kp, *Vp, *Ap;
    __half *hid2, *att2, *wq2, *wk2, *wv2, *wo2;
    __half *qh, *ql, *kh, *kl, *vh, *vl;
    cudaGetSymbolAddress((void**)&Qp, g_Q);
    cudaGetSymbolAddress((void**)&Kp, g_K);
    cudaGetSymbolAddress((void**)&Vp, g_V);
    cudaGetSymbolAddress((void**)&Ap, g_A);
    cudaGetSymbolAddress((void**)&hid2, g_hid2);
    cudaGetSymbolAddress((void**)&att2, g_att2);
    cudaGetSymbolAddress((void**)&wq2, g_Wq2);
    cudaGetSymbolAddress((void**)&wk2, g_Wk2);
    cudaGetSymbolAddress((void**)&wv2, g_Wv2);
    cudaGetSymbolAddress((void**)&wo2, g_Wo2);
    cudaGetSymbolAddress((void**)&qh, g_Qh);
    cudaGetSymbolAddress((void**)&ql, g_Ql);
    cudaGetSymbolAddress((void**)&kh, g_Kh);
    cudaGetSymbolAddress((void**)&kl, g_Kl);
    cudaGetSymbolAddress((void**)&vh, g_Vh);
    cudaGetSymbolAddress((void**)&vl, g_Vl);

    const int M = CB * CS;                 // 8192
    const int tot = M * KK;

    cudaFuncSetAttribute(mma_gemm, cudaFuncAttributeMaxDynamicSharedMemorySize,
                         GEMM_SMEM_BYTES);
    cudaFuncSetAttribute(attn_mma, cudaFuncAttributeMaxDynamicSharedMemorySize,
                         AT_SMEM_BYTES);

    // conversions
    cvt_hilo_rows<<<(tot + 255) / 256, 256>>>(hidden, hid2, tot);
    cvt_T_h<<<dim3(CHID / 32, KK / 32), dim3(32, 8)>>>(Wq, wq2, CHID);
    cvt_T_h<<<dim3((CKV * CD) / 32, KK / 32), dim3(32, 8)>>>(Wk, wk2, CKV * CD);
    cvt_T_h<<<dim3((CKV * CD) / 32, KK / 32), dim3(32, 8)>>>(Wv, wv2, CKV * CD);
    cvt_T_h<<<dim3(CHID / 32, KK / 32), dim3(32, 8)>>>(Wo, wo2, CHID);

    // QKV projections
    mma_gemm<<<dim3(CHID / 128, M / 128), 256, GEMM_SMEM_BYTES>>>(hid2, wq2, Qp, M, CHID);
    mma_gemm<<<dim3((CKV * CD) / 128, M / 128), 256, GEMM_SMEM_BYTES>>>(hid2, wk2, Kp, M, CKV * CD);
    mma_gemm<<<dim3((CKV * CD) / 128, M / 128), 256, GEMM_SMEM_BYTES>>>(hid2, wv2, Vp, M, CKV * CD);

    // RoPE + hi/lo split (Q scaled), V split
    rope_split<<<(CB * CS * CH * 64) / 256, 256>>>(Qp, cosb, sinb, qh, ql, CH, QK_SCALE);
    rope_split<<<(CB * CS * CKV * 64) / 256, 256>>>(Kp, cosb, sinb, kh, kl, CKV, 1.0f);
    cvt_split<<<(CB * CS * CKV * CD + 255) / 256, 256>>>(Vp, vh, vl, CB * CS * CKV * CD);

    // attention (tensor cores)
    attn_mma<<<dim3(CNB, CH, CB), 256, AT_SMEM_BYTES>>>(qh, ql, kh, kl, vh, vl, amask, Ap);

    // output projection
    cvt_hilo_rows<<<(tot + 255) / 256, 256>>>(Ap, att2, tot);
    mma_gemm<<<dim3(CHID / 128, M / 128), 256, GEMM_SMEM_BYTES>>>(att2, wo2, out, M, CHID);
}

// round 14
// speedup vs baseline: 6.7493x; 1.5296x over previous
#include <cuda_runtime.h>
#include <cuda_fp16.h>
#include <math.h>
#include <stdint.h>

#define CB   2
#define CS   4096
#define CHID 2048
#define CH   16
#define CKV  4
#define CD   128
#define CNB  64
#define NEGV -1000000000.0f
#define QK_SCALE 0.08838834764831845f   // 1/sqrt(128)

#define KK   2048

// -------- scratch (static device memory; allocation-free rule) --------
static __device__ float g_Q[(size_t)CB*CS*CH*CD];          // QKV GEMM outs fp32
static __device__ float g_K[(size_t)CB*CS*CKV*CD];
static __device__ float g_V[(size_t)CB*CS*CKV*CD];
static __device__ __half g_hid[(size_t)CB*CS*KK];          // hidden fp16 [8192,2048]
static __device__ __half g_att[(size_t)CB*CS*KK];          // attn out fp16 [8192,2048]
static __device__ __half g_Wq2[(size_t)CHID*KK];           // [N, K] fp16
static __device__ __half g_Wk2[(size_t)CKV*CD*KK];
static __device__ __half g_Wv2[(size_t)CKV*CD*KK];
static __device__ __half g_Wo2[(size_t)CHID*KK];
// fp16 hi/lo attention operands
static __device__ __half g_Qh[(size_t)CB*CS*CH*CD];
static __device__ __half g_Ql[(size_t)CB*CS*CH*CD];
static __device__ __half g_Kh[(size_t)CB*CS*CKV*CD];
static __device__ __half g_Kl[(size_t)CB*CS*CKV*CD];
static __device__ __half g_Vh[(size_t)CB*CS*CKV*CD];
static __device__ __half g_Vl[(size_t)CB*CS*CKV*CD];

// ============================================================
// portable async-copy / ldmatrix / mma helpers
// ============================================================
__device__ __forceinline__ uint32_t smem_u32(const void* p) {
    uint32_t a;
    asm("{ .reg .u64 t; cvta.to.shared.u64 t, %1; cvt.u32.u64 %0, t; }"
        : "=r"(a) : "l"(p));
    return a;
}
__device__ __forceinline__ void cp16(uint32_t dst, const void* src) {
    asm volatile("cp.async.cg.shared.global [%0], [%1], 16;"
                 :: "r"(dst), "l"(src) : "memory");
}
__device__ __forceinline__ void cp_commit() {
    asm volatile("cp.async.commit_group;" ::: "memory");
}
template<int N_> __device__ __forceinline__ void cp_wait() {
    asm volatile("cp.async.wait_group %0;" :: "n"(N_) : "memory");
}
__device__ __forceinline__ void bar_g(int id) {
    asm volatile("bar.sync %0, 128;" :: "r"(id) : "memory");
}
#define LDSM4(r, addr) \
    asm volatile("ldmatrix.sync.aligned.m8n8.x4.shared.b16 {%0,%1,%2,%3}, [%4];" \
        : "=r"((r)[0]), "=r"((r)[1]), "=r"((r)[2]), "=r"((r)[3]) : "r"(addr))
#define LDSM4T(r, addr) \
    asm volatile("ldmatrix.sync.aligned.m8n8.x4.trans.shared.b16 {%0,%1,%2,%3}, [%4];" \
        : "=r"((r)[0]), "=r"((r)[1]), "=r"((r)[2]), "=r"((r)[3]) : "r"(addr))
#define MMA16816(d, a, b0, b1) \
    asm volatile("mma.sync.aligned.m16n8k16.row.col.f32.f16.f16.f32 " \
        "{%0,%1,%2,%3}, {%4,%5,%6,%7}, {%8,%9}, {%0,%1,%2,%3};" \
        : "+f"((d)[0]), "+f"((d)[1]), "+f"((d)[2]), "+f"((d)[3]) \
        : "r"((a)[0]), "r"((a)[1]), "r"((a)[2]), "r"((a)[3]), "r"(b0), "r"(b1))

__device__ __forceinline__ uint32_t packh2(__half a, __half b) {
    __half2 t = __halves2half2(a, b);
    return *reinterpret_cast<uint32_t*>(&t);
}

// ============================================================
// fp16 mma.sync GEMM (single pass):
//   C[M,N] = A@B^T     A [M,K] fp16 row-major, B [N,K] fp16 row-major.
// CTA tile 128x128, BK=64, 3-stage cp.async pipeline, 8 warps.
// ============================================================
#define GSTG    3
#define GSTRIDE 32768
#define GEMM_SMEM_BYTES (GSTG * GSTRIDE + 1024)
#define NCHUNK  32

__global__ __launch_bounds__(256) void mma_gemm(
    const __half* __restrict__ Ab,
    const __half* __restrict__ Bb,
    float* __restrict__ C, int M, int N)
{
    extern __shared__ char dsm_raw[];
    char* dsm = (char*)(((uintptr_t)dsm_raw + 1023) & ~(uintptr_t)1023);
    const uint32_t sb = smem_u32(dsm);

    const int tid  = threadIdx.x;
    const int lane = tid & 31;
    const int w    = tid >> 5;
    const int bx = blockIdx.x * 128;
    const int by = blockIdx.y * 128;
    const int wm = (w >> 2) * 64;
    const int wn = (w & 3) * 32;

    uint32_t aAddr[4];
#pragma unroll
    for (int mt = 0; mt < 4; ++mt) {
        int r = wm + mt * 16 + (lane & 15);
        aAddr[mt] = sb + (uint32_t)r * 128;
    }
    const uint32_t aSw  = (uint32_t)(((wm + (lane & 15)) & 7) << 4);
    const uint32_t aCb0 = (uint32_t)((lane >> 4) * 16);
    uint32_t bAddr[2];
    {
        int n = wn + (lane & 7) + ((lane >> 4) << 3);
        bAddr[0] = sb + 16384 + (uint32_t)n * 128;
        bAddr[1] = bAddr[0] + 16 * 128;
    }
    const uint32_t bSw  = (uint32_t)((((lane & 7) + ((lane >> 4) << 3)) & 7) << 4);
    const uint32_t bCb0 = (uint32_t)(((lane >> 3) & 1) * 16);

    float acc[4][4][4];
#pragma unroll
    for (int mt = 0; mt < 4; ++mt)
#pragma unroll
        for (int nt = 0; nt < 4; ++nt)
#pragma unroll
            for (int e = 0; e < 4; ++e) acc[mt][nt][e] = 0.f;

    auto load_chunk = [&](int c, int stage) {
        const int k0 = c * 64;
        const uint32_t sBase = sb + (uint32_t)stage * GSTRIDE;
#pragma unroll
        for (int i = 0; i < 4; ++i) {
            const int id  = tid + i * 256;
            const int row = id >> 3;
            const int ch  = id & 7;
            const uint32_t soff = (uint32_t)row * 128
                                + (uint32_t)((ch * 16) ^ ((row & 7) << 4));
            cp16(sBase + soff,
                 Ab + (size_t)(by + row) * KK + k0 + ch * 8);
            cp16(sBase + 16384 + soff,
                 Bb + (size_t)(bx + row) * KK + k0 + ch * 8);
        }
    };

    load_chunk(0, 0); cp_commit();
    load_chunk(1, 1); cp_commit();

    for (int c = 0; c < NCHUNK; ++c) {
        cp_wait<1>();
        __syncthreads();
        if (c + 2 < NCHUNK) load_chunk(c + 2, (c + 2) % GSTG);
        cp_commit();

        const uint32_t st = (uint32_t)(c % GSTG) * GSTRIDE;
#pragma unroll
        for (int j = 0; j < 4; ++j) {
            const uint32_t akb = ((uint32_t)(j * 32) + aCb0) ^ aSw;
            const uint32_t bkb = ((uint32_t)(j * 32) + bCb0) ^ bSw;
            uint32_t afr[4][4], bfr[2][4];
#pragma unroll
            for (int mt = 0; mt < 4; ++mt)
                LDSM4(afr[mt], aAddr[mt] + st + akb);
#pragma unroll
            for (int ld = 0; ld < 2; ++ld)
                LDSM4(bfr[ld], bAddr[ld] + st + bkb);
#pragma unroll
            for (int mt = 0; mt < 4; ++mt) {
#pragma unroll
                for (int nt = 0; nt < 4; ++nt) {
                    const uint32_t* bf = bfr[nt >> 1];
                    const int p = (nt & 1) * 2;
                    MMA16816(acc[mt][nt], afr[mt], bf[p], bf[p + 1]);
                }
            }
        }
    }

    const int crow = lane >> 2;
    const int ccol = (lane & 3) * 2;
#pragma unroll
    for (int mt = 0; mt < 4; ++mt) {
#pragma unroll
        for (int nt = 0; nt < 4; ++nt) {
            float* cp = C + (size_t)(by + wm + mt * 16 + crow) * N
                          + bx + wn + nt * 8 + ccol;
            *(float2*)cp = make_float2(acc[mt][nt][0], acc[mt][nt][1]);
            *(float2*)(cp + (size_t)8 * N) = make_float2(acc[mt][nt][2], acc[mt][nt][3]);
        }
    }
}

// ============================================================
// conversion kernels
// ============================================================
__global__ void cvt_h(const float* __restrict__ X, __half* __restrict__ Y, int total)
{
    int idx = blockIdx.x * blockDim.x + threadIdx.x;
    if (idx >= total) return;
    Y[idx] = __float2half_rn(X[idx]);
}

__global__ void cvt_T_h(const float* __restrict__ W,
                        __half* __restrict__ Y, int N)
{
    __shared__ float t[32][33];
    const int k0 = blockIdx.y * 32, n0 = blockIdx.x * 32;
    const int tx = threadIdx.x, ty = threadIdx.y;
#pragma unroll
    for (int j = 0; j < 32; j += 8)
        t[ty + j][tx] = W[(size_t)(k0 + ty + j) * N + n0 + tx];
    __syncthreads();
#pragma unroll
    for (int j = 0; j < 32; j += 8)
        Y[(size_t)(n0 + ty + j) * KK + k0 + tx] = __float2half_rn(t[tx][ty + j]);
}

// RoPE + hi/lo split: X fp32 [B*S, nh, D] -> Yh/Yl fp16
__global__ void rope_split(const float* __restrict__ X,
                           const float* __restrict__ cs, const float* __restrict__ sn,
                           __half* __restrict__ Yh, __half* __restrict__ Yl,
                           int nh, float scale)
{
    int idx = blockIdx.x * blockDim.x + threadIdx.x;
    int total = CB * CS * nh * (CD / 2);
    if (idx >= total) return;
    int d = idx & 63;
    int h = (idx >> 6) % nh;
    int t = idx / (64 * nh);
    const float* c = cs + (size_t)t * CD;
    const float* s = sn + (size_t)t * CD;
    const float* x = X + ((size_t)t * nh + h) * CD;
    size_t o = ((size_t)t * nh + h) * CD;
    float x1 = x[d], x2 = x[d + 64];
    float v1 = (x1 * c[d]      - x2 * s[d])      * scale;
    float v2 = (x2 * c[d + 64] + x1 * s[d + 64]) * scale;
    __half h1 = __float2half_rn(v1), h2 = __float2half_rn(v2);
    Yh[o + d] = h1;      Yl[o + d] = __float2half_rn(v1 - __half2float(h1));
    Yh[o + d + 64] = h2; Yl[o + d + 64] = __float2half_rn(v2 - __half2float(h2));
}

__global__ void cvt_split(const float* __restrict__ X,
                          __half* __restrict__ Yh, __half* __restrict__ Yl, int total)
{
    int idx = blockIdx.x * blockDim.x + threadIdx.x;
    if (idx >= total) return;
    float x = X[idx];
    __half h = __float2half_rn(x);
    Yh[idx] = h;
    Yl[idx] = __float2half_rn(x - __half2float(h));
}

// ============================================================
// Tensor-core sparse attention. grid=(NB,H,B), 256 threads.
// Warps 0-3 (group 0): local chunks; warps 4-7 (group 1): global.
// Split-softmax merge at end; fp16 output (feeds Wo GEMM directly).
// ============================================================
#define AT_SMEM_BYTES (163840 + 1024)

__device__ __forceinline__ uint32_t soff256(int row, uint32_t ch) {
    return (uint32_t)row * 256 + ((ch ^ (uint32_t)(row & 7)) << 4);
}

__global__ __launch_bounds__(256) void attn_mma(
    const __half* __restrict__ Qh_, const __half* __restrict__ Ql_,
    const __half* __restrict__ Kh_, const __half* __restrict__ Kl_,
    const __half* __restrict__ Vh_, const __half* __restrict__ Vl_,
    const float* __restrict__ am, __half* __restrict__ Aout)
{
    extern __shared__ char dsm_raw[];
    char* dsm = (char*)(((uintptr_t)dsm_raw + 1023) & ~(uintptr_t)1023);
    __shared__ float sM[2][64], sL[2][64], sKM[2][64];

    const int i = blockIdx.x, h = blockIdx.y, b = blockIdx.z;
    const int kvh = h >> 2;
    const int tid = threadIdx.x, lane = tid & 31, wid = tid >> 5;
    const int g = wid >> 2, w4 = wid & 3, wrow = w4 * 16;
    const int gtid = tid & 127;

    const uint32_t sQh = smem_u32(dsm);
    const uint32_t sQl = sQh + 16384;
    const uint32_t sKh = sQh + 32768 + (uint32_t)g * 65536;
    const uint32_t sKl = sKh + 16384;
    const uint32_t sVh = sKh + 32768;
    const uint32_t sVl = sKh + 49152;
    float* smO = (float*)(dsm + 32768);

    const __half* qhg = Qh_ + (((size_t)b * CS + (size_t)i * 64) * CH + h) * CD;
    const __half* qlg = Ql_ + (((size_t)b * CS + (size_t)i * 64) * CH + h) * CD;
    for (int e = tid; e < 1024; e += 256) {
        int row = e >> 4; uint32_t ch = (uint32_t)(e & 15);
        uint32_t off = soff256(row, ch);
        cp16(sQh + off, qhg + (size_t)row * CH * CD + ch * 8);
        cp16(sQl + off, qlg + (size_t)row * CH * CD + ch * 8);
    }

    auto chunk_info = [&](int ci, int& kb, bool& intra) -> bool {
        if (g == 0) {
            kb = i - 3 + ci;
            intra = (ci == 3);
            return kb >= 0;
        } else {
            intra = false;
            int lo = (i > 32) ? (i - 32) : 0;
            int cnt = (i - lo + 3) >> 2;
            int j = cnt - 4 + ci;
            kb = lo + 4 * j;
            return (i >= 1) && (j >= 0);
        }
    };

    auto load_kv = [&](int kb) {
        const size_t base = (((size_t)b * CS + (size_t)kb * 64) * CKV + kvh) * CD;
        for (int e = gtid; e < 1024; e += 128) {
            int row = e >> 4; uint32_t ch = (uint32_t)(e & 15);
            uint32_t off = soff256(row, ch);
            size_t so = base + (size_t)row * CKV * CD + ch * 8;
            cp16(sKh + off, Kh_ + so);
            cp16(sKl + off, Kl_ + so);
            cp16(sVh + off, Vh_ + so);
            cp16(sVl + off, Vl_ + so);
        }
        if (gtid < 64) sKM[g][gtid] = am[(size_t)b * CS + (size_t)kb * 64 + gtid];
    };

    float O[16][4];
#pragma unroll
    for (int nt = 0; nt < 16; ++nt)
#pragma unroll
        for (int e = 0; e < 4; ++e) O[nt][e] = 0.f;
    float m0 = -1e30f, l0 = 0.f, m1 = -1e30f, l1 = 0.f;

    const int rl = lane >> 2;
    const int row0 = wrow + rl, row1 = row0 + 8;

    {
        int kb; bool intra;
        if (chunk_info(0, kb, intra)) load_kv(kb);
    }
    cp_commit(); cp_wait<0>();
    __syncthreads();

    for (int ci = 0; ci < 4; ++ci) {
        int kb; bool intra;
        bool valid = chunk_info(ci, kb, intra);
        if (ci > 0) {
            bar_g(g + 1);
            if (valid) load_kv(kb);
            cp_commit(); cp_wait<0>();
            bar_g(g + 1);
        }
        if (!valid) continue;

        float S[8][4];
#pragma unroll
        for (int nt = 0; nt < 8; ++nt)
#pragma unroll
            for (int e = 0; e < 4; ++e) S[nt][e] = 0.f;

#pragma unroll
        for (int ks = 0; ks < 8; ++ks) {
            int qrow = wrow + (lane & 15);
            uint32_t qoff = soff256(qrow, (uint32_t)(2 * ks + (lane >> 4)));
            uint32_t qh[4], ql[4];
            LDSM4(qh, sQh + qoff);
            LDSM4(ql, sQl + qoff);
#pragma unroll
            for (int nt2 = 0; nt2 < 4; ++nt2) {
                int n = nt2 * 16 + (lane & 7) + ((lane >> 4) << 3);
                uint32_t koff = soff256(n, (uint32_t)(2 * ks + ((lane >> 3) & 1)));
                uint32_t bh[4], bl[4];
                LDSM4(bh, sKh + koff);
                MMA16816(S[nt2 * 2],     qh, bh[0], bh[1]);
                MMA16816(S[nt2 * 2 + 1], qh, bh[2], bh[3]);
                MMA16816(S[nt2 * 2],     ql, bh[0], bh[1]);
                MMA16816(S[nt2 * 2 + 1], ql, bh[2], bh[3]);
                LDSM4(bl, sKl + koff);
                MMA16816(S[nt2 * 2],     qh, bl[0], bl[1]);
                MMA16816(S[nt2 * 2 + 1], qh, bl[2], bl[3]);
            }
        }

#pragma unroll
        for (int nt = 0; nt < 8; ++nt) {
            int c0 = nt * 8 + 2 * (lane & 3);
            float km0 = sKM[g][c0], km1 = sKM[g][c0 + 1];
            S[nt][0] += (1.0f - km0) * NEGV;
            S[nt][1] += (1.0f - km1) * NEGV;
            S[nt][2] += (1.0f - km0) * NEGV;
            S[nt][3] += (1.0f - km1) * NEGV;
            if (intra) {
                if (c0 > row0)     S[nt][0] += NEGV;
                if (c0 + 1 > row0) S[nt][1] += NEGV;
                if (c0 > row1)     S[nt][2] += NEGV;
                if (c0 + 1 > row1) S[nt][3] += NEGV;
            }
        }

        float mx0 = -1e30f, mx1 = -1e30f;
#pragma unroll
        for (int nt = 0; nt < 8; ++nt) {
            mx0 = fmaxf(mx0, fmaxf(S[nt][0], S[nt][1]));
            mx1 = fmaxf(mx1, fmaxf(S[nt][2], S[nt][3]));
        }
#pragma unroll
        for (int o = 1; o < 4; o <<= 1) {
            mx0 = fmaxf(mx0, __shfl_xor_sync(0xffffffffu, mx0, o));
            mx1 = fmaxf(mx1, __shfl_xor_sync(0xffffffffu, mx1, o));
        }
        float mn0 = fmaxf(m0, mx0), mn1 = fmaxf(m1, mx1);
        float a0 = __expf(m0 - mn0), a1 = __expf(m1 - mn1);
        float s0 = 0.f, s1 = 0.f;
#pragma unroll
        for (int nt = 0; nt < 8; ++nt) {
            S[nt][0] = __expf(S[nt][0] - mn0);
            S[nt][1] = __expf(S[nt][1] - mn0);
            S[nt][2] = __expf(S[nt][2] - mn1);
            S[nt][3] = __expf(S[nt][3] - mn1);
            s0 += S[nt][0] + S[nt][1];
            s1 += S[nt][2] + S[nt][3];
        }
#pragma unroll
        for (int o = 1; o < 4; o <<= 1) {
            s0 += __shfl_xor_sync(0xffffffffu, s0, o);
            s1 += __shfl_xor_sync(0xffffffffu, s1, o);
        }
        l0 = l0 * a0 + s0;
        l1 = l1 * a1 + s1;
        m0 = mn0; m1 = mn1;
#pragma unroll
        for (int nt = 0; nt < 16; ++nt) {
            O[nt][0] *= a0; O[nt][1] *= a0;
            O[nt][2] *= a1; O[nt][3] *= a1;
        }

#pragma unroll
        for (int kt = 0; kt < 4; ++kt) {
            uint32_t ph[4], pl[4];
#pragma unroll
            for (int jj = 0; jj < 2; ++jj) {
                int t_ = 2 * kt + jj;
                __half h0 = __float2half_rn(S[t_][0]);
                __half h1 = __float2half_rn(S[t_][1]);
                __half h2 = __float2half_rn(S[t_][2]);
                __half h3 = __float2half_rn(S[t_][3]);
                __half e0 = __float2half_rn(S[t_][0] - __half2float(h0));
                __half e1 = __float2half_rn(S[t_][1] - __half2float(h1));
                __half e2 = __float2half_rn(S[t_][2] - __half2float(h2));
                __half e3 = __float2half_rn(S[t_][3] - __half2float(h3));
                ph[jj * 2]     = packh2(h0, h1);
                ph[jj * 2 + 1] = packh2(h2, h3);
                pl[jj * 2]     = packh2(e0, e1);
                pl[jj * 2 + 1] = packh2(e2, e3);
            }
            uint32_t pA[4] = { ph[0], ph[1], ph[2], ph[3] };
            uint32_t pB[4] = { pl[0], pl[1], pl[2], pl[3] };
            int key = 16 * kt + (lane & 15);
#pragma unroll
            for (int nd2 = 0; nd2 < 8; ++nd2) {
                uint32_t voff = soff256(key, (uint32_t)(2 * nd2 + (lane >> 4)));
                uint32_t vh[4], vl[4];
                LDSM4T(vh, sVh + voff);
                MMA16816(O[nd2 * 2],     pA, vh[0], vh[1]);
                MMA16816(O[nd2 * 2 + 1], pA, vh[2], vh[3]);
                MMA16816(O[nd2 * 2],     pB, vh[0], vh[1]);
                MMA16816(O[nd2 * 2 + 1], pB, vh[2], vh[3]);
                LDSM4T(vl, sVl + voff);
                MMA16816(O[nd2 * 2],     pA, vl[0], vl[1]);
                MMA16816(O[nd2 * 2 + 1], pA, vl[2], vl[3]);
            }
        }
    }

    // ---- split-softmax merge, fp16 output ----
    __syncthreads();
    if ((lane & 3) == 0) {
        sM[g][row0] = m0; sL[g][row0] = l0;
        sM[g][row1] = m1; sL[g][row1] = l1;
    }
    __syncthreads();
    float mA0 = sM[0][row0], mB0 = sM[1][row0];
    float mA1 = sM[0][row1], mB1 = sM[1][row1];
    float mt0 = fmaxf(mA0, mB0), mt1 = fmaxf(mA1, mB1);
    float fA0 = __expf(mA0 - mt0), fB0 = __expf(mB0 - mt0);
    float fA1 = __expf(mA1 - mt1), fB1 = __expf(mB1 - mt1);
    float den0 = sL[0][row0] * fA0 + sL[1][row0] * fB0;
    float den1 = sL[0][row1] * fA1 + sL[1][row1] * fB1;

    if (g == 1) {
#pragma unroll
        for (int nt = 0; nt < 16; ++nt) {
            int c0 = nt * 8 + 2 * (lane & 3);
            smO[row0 * 128 + c0]     = O[nt][0] * fB0;
            smO[row0 * 128 + c0 + 1] = O[nt][1] * fB0;
            smO[row1 * 128 + c0]     = O[nt][2] * fB1;
            smO[row1 * 128 + c0 + 1] = O[nt][3] * fB1;
        }
    }
    __syncthreads();
    if (g == 0) {
        __half* og = Aout + (((size_t)b * CS + (size_t)i * 64) * CH + h) * CD;
        float r0 = 1.0f / den0, r1 = 1.0f / den1;
#pragma unroll
        for (int nt = 0; nt < 16; ++nt) {
            int c0 = nt * 8 + 2 * (lane & 3);
            float o00 = (O[nt][0] * fA0 + smO[row0 * 128 + c0])     * r0;
            float o01 = (O[nt][1] * fA0 + smO[row0 * 128 + c0 + 1]) * r0;
            float o10 = (O[nt][2] * fA1 + smO[row1 * 128 + c0])     * r1;
            float o11 = (O[nt][3] * fA1 + smO[row1 * 128 + c0 + 1]) * r1;
            *(__half2*)(og + (size_t)row0 * CH * CD + c0) = __floats2half2_rn(o00, o01);
            *(__half2*)(og + (size_t)row1 * CH * CD + c0) = __floats2half2_rn(o10, o11);
        }
    }
}

// ============================================================
// launcher
// ============================================================
extern "C" void kernel_launch(void* const* d_in, const int* in_sizes, int n_in,
                              void* d_out, int out_size)
{
    (void)in_sizes; (void)n_in; (void)out_size;
    const float* hidden = (const float*)d_in[0];
    const float* cosb   = (const float*)d_in[1];
    const float* sinb   = (const float*)d_in[2];
    const float* amask  = (const float*)d_in[3];
    const float* Wq     = (const float*)d_in[4];
    const float* Wk     = (const float*)d_in[5];
    const float* Wv     = (const float*)d_in[6];
    const float* Wo     = (const float*)d_in[7];
    float* out = (float*)d_out;

    float *Qp, *Kp, *Vp;
    __half *hid, *att, *wq2, *wk2, *wv2, *wo2;
    __half *qh, *ql, *kh, *kl, *vh, *vl;
    cudaGetSymbolAddress((void**)&Qp, g_Q);
    cudaGetSymbolAddress((void**)&Kp, g_K);
    cudaGetSymbolAddress((void**)&Vp, g_V);
    cudaGetSymbolAddress((void**)&hid, g_hid);
    cudaGetSymbolAddress((void**)&att, g_att);
    cudaGetSymbolAddress((void**)&wq2, g_Wq2);
    cudaGetSymbolAddress((void**)&wk2, g_Wk2);
    cudaGetSymbolAddress((void**)&wv2, g_Wv2);
    cudaGetSymbolAddress((void**)&wo2, g_Wo2);
    cudaGetSymbolAddress((void**)&qh, g_Qh);
    cudaGetSymbolAddress((void**)&ql, g_Ql);
    cudaGetSymbolAddress((void**)&kh, g_Kh);
    cudaGetSymbolAddress((void**)&kl, g_Kl);
    cudaGetSymbolAddress((void**)&vh, g_Vh);
    cudaGetSymbolAddress((void**)&vl, g_Vl);

    const int M = CB * CS;                 // 8192
    const int tot = M * KK;

    cudaFuncSetAttribute(mma_gemm, cudaFuncAttributeMaxDynamicSharedMemorySize,
                         GEMM_SMEM_BYTES);
    cudaFuncSetAttribute(attn_mma, cudaFuncAttributeMaxDynamicSharedMemorySize,
                         AT_SMEM_BYTES);

    // conversions
    cvt_h<<<(tot + 255) / 256, 256>>>(hidden, hid, tot);
    cvt_T_h<<<dim3(CHID / 32, KK / 32), dim3(32, 8)>>>(Wq, wq2, CHID);
    cvt_T_h<<<dim3((CKV * CD) / 32, KK / 32), dim3(32, 8)>>>(Wk, wk2, CKV * CD);
    cvt_T_h<<<dim3((CKV * CD) / 32, KK / 32), dim3(32, 8)>>>(Wv, wv2, CKV * CD);
    cvt_T_h<<<dim3(CHID / 32, KK / 32), dim3(32, 8)>>>(Wo, wo2, CHID);

    // QKV projections (single-pass fp16)
    mma_gemm<<<dim3(CHID / 128, M / 128), 256, GEMM_SMEM_BYTES>>>(hid, wq2, Qp, M, CHID);
    mma_gemm<<<dim3((CKV * CD) / 128, M / 128), 256, GEMM_SMEM_BYTES>>>(hid, wk2, Kp, M, CKV * CD);
    mma_gemm<<<dim3((CKV * CD) / 128, M / 128), 256, GEMM_SMEM_BYTES>>>(hid, wv2, Vp, M, CKV * CD);

    // RoPE + hi/lo split (Q scaled), V split
    rope_split<<<(CB * CS * CH * 64) / 256, 256>>>(Qp, cosb, sinb, qh, ql, CH, QK_SCALE);
    rope_split<<<(CB * CS * CKV * 64) / 256, 256>>>(Kp, cosb, sinb, kh, kl, CKV, 1.0f);
    cvt_split<<<(CB * CS * CKV * CD + 255) / 256, 256>>>(Vp, vh, vl, CB * CS * CKV * CD);

    // attention (tensor cores) -> fp16 directly
    attn_mma<<<dim3(CNB, CH, CB), 256, AT_SMEM_BYTES>>>(qh, ql, kh, kl, vh, vl, amask, att);

    // output projection
    mma_gemm<<<dim3(CHID / 128, M / 128), 256, GEMM_SMEM_BYTES>>>(att, wo2, out, M, CHID);
}